// round 1
// baseline (speedup 1.0000x reference)
#include <cuda_runtime.h>
#include <cstdint>
#include <cstddef>

// Problem constants
constexpr int Bc  = 2;
constexpr int Sc  = 2048;
constexpr int HS  = 2048;
constexpr int NHc = 16;
constexpr int HDc = 128;
constexpr int MR  = Bc * Sc;    // 4096 rows of (b, s)
constexpr int BHc = Bc * NHc;   // 32 (batch*heads)
constexpr float SCALE = 0.08838834764831845f;  // 1/sqrt(128)

// Scratch (device globals — allocation-free per harness rules)
__device__ float g_q [MR * HS];
__device__ float g_k [MR * HS];
__device__ float g_v [MR * HS];
__device__ float g_ao[MR * HS];
__device__ float g_sc[(size_t)BHc * Sc * Sc];   // 512 MB scores/probs

// ---------------------------------------------------------------------------
// TF32 helpers
// ---------------------------------------------------------------------------
__device__ __forceinline__ uint32_t f2t(float x) {
    uint32_t r;
    asm("cvt.rna.tf32.f32 %0, %1;" : "=r"(r) : "f"(x));
    return r;
}

__device__ __forceinline__ void mma8(float* c, const uint32_t* a, const uint32_t* b) {
    asm volatile(
        "mma.sync.aligned.m16n8k8.row.col.f32.tf32.tf32.f32 "
        "{%0,%1,%2,%3},{%4,%5,%6,%7},{%8,%9},{%0,%1,%2,%3};\n"
        : "+f"(c[0]), "+f"(c[1]), "+f"(c[2]), "+f"(c[3])
        : "r"(a[0]), "r"(a[1]), "r"(a[2]), "r"(a[3]),
          "r"(b[0]), "r"(b[1]));
}

// ---------------------------------------------------------------------------
// Shared TN mainloop: C(128x128) += A(128xK) * B(128xK)^T, BK=32
// sA/sB hold tf32-rounded bits, padded to 36 cols (conflict-free frag loads)
// ---------------------------------------------------------------------------
__device__ __forceinline__ void mainloop_tn(
    const float* __restrict__ Ab, const float* __restrict__ Bb,
    int lda, int ldb, int K,
    uint32_t (&sA)[128][36], uint32_t (&sB)[128][36],
    float (&acc)[2][8][4])
{
    const int tid  = threadIdx.x;
    const int lane = tid & 31, warp = tid >> 5;
    const int g = lane >> 2, tg = lane & 3;
    const int wm = (warp & 3) * 32, wn = (warp >> 2) * 64;
    const int lr = tid >> 3, lc = (tid & 7) * 4;

    for (int k0 = 0; k0 < K; k0 += 32) {
#pragma unroll
        for (int i = 0; i < 4; i++) {
            int r = lr + i * 32;
            float4 va = *(const float4*)(Ab + (size_t)r * lda + k0 + lc);
            sA[r][lc + 0] = f2t(va.x); sA[r][lc + 1] = f2t(va.y);
            sA[r][lc + 2] = f2t(va.z); sA[r][lc + 3] = f2t(va.w);
            float4 vb = *(const float4*)(Bb + (size_t)r * ldb + k0 + lc);
            sB[r][lc + 0] = f2t(vb.x); sB[r][lc + 1] = f2t(vb.y);
            sB[r][lc + 2] = f2t(vb.z); sB[r][lc + 3] = f2t(vb.w);
        }
        __syncthreads();
#pragma unroll
        for (int ks = 0; ks < 4; ks++) {
            uint32_t af[2][4];
#pragma unroll
            for (int mi = 0; mi < 2; mi++) {
                int r = wm + mi * 16 + g, c = ks * 8 + tg;
                af[mi][0] = sA[r][c];     af[mi][1] = sA[r + 8][c];
                af[mi][2] = sA[r][c + 4]; af[mi][3] = sA[r + 8][c + 4];
            }
            uint32_t bf[8][2];
#pragma unroll
            for (int ni = 0; ni < 8; ni++) {
                int n = wn + ni * 8 + g, c = ks * 8 + tg;
                bf[ni][0] = sB[n][c]; bf[ni][1] = sB[n][c + 4];
            }
#pragma unroll
            for (int mi = 0; mi < 2; mi++)
#pragma unroll
                for (int ni = 0; ni < 8; ni++)
                    mma8(acc[mi][ni], af[mi], bf[ni]);
        }
        __syncthreads();
    }
}

// ---------------------------------------------------------------------------
// Generic projection GEMM: C[M,N] = A[M,K] * B[N,K]^T  (all row-major)
// grid = (N/128, M/128), block = 256
// ---------------------------------------------------------------------------
__global__ __launch_bounds__(256) void gemm_tn(
    const float* __restrict__ A, const float* __restrict__ B,
    float* __restrict__ C, int lda, int ldb, int ldc, int K)
{
    __shared__ uint32_t sA[128][36];
    __shared__ uint32_t sB[128][36];
    float acc[2][8][4];
#pragma unroll
    for (int mi = 0; mi < 2; mi++)
#pragma unroll
        for (int ni = 0; ni < 8; ni++)
#pragma unroll
            for (int j = 0; j < 4; j++) acc[mi][ni][j] = 0.f;

    const float* Ab = A + (size_t)blockIdx.y * 128 * lda;
    const float* Bb = B + (size_t)blockIdx.x * 128 * ldb;
    mainloop_tn(Ab, Bb, lda, ldb, K, sA, sB, acc);

    const int tid = threadIdx.x, lane = tid & 31, warp = tid >> 5;
    const int g = lane >> 2, tg = lane & 3;
    const int wm = (warp & 3) * 32, wn = (warp >> 2) * 64;
    const size_t rbase = (size_t)blockIdx.y * 128;
    const int cbase = blockIdx.x * 128;
#pragma unroll
    for (int mi = 0; mi < 2; mi++)
#pragma unroll
        for (int ni = 0; ni < 8; ni++) {
            size_t r = rbase + wm + mi * 16 + g;
            int    c = cbase + wn + ni * 8 + tg * 2;
            float2 v0; v0.x = acc[mi][ni][0]; v0.y = acc[mi][ni][1];
            float2 v1; v1.x = acc[mi][ni][2]; v1.y = acc[mi][ni][3];
            *(float2*)(C + r * ldc + c)       = v0;
            *(float2*)(C + (r + 8) * ldc + c) = v1;
        }
}

// ---------------------------------------------------------------------------
// RoPE (in place on Q and K). grid = (MR*NH*64/256, 2), blockIdx.y: 0=Q 1=K
// ---------------------------------------------------------------------------
__global__ __launch_bounds__(256) void rope_kernel(
    float* __restrict__ q, float* __restrict__ k,
    const float* __restrict__ cb, const float* __restrict__ sb)
{
    int i = blockIdx.x * 256 + threadIdx.x;       // over MR*NH*64
    float* arr = blockIdx.y ? k : q;
    int d   = i & 63;
    int h   = (i >> 6) & (NHc - 1);
    int row = i >> 10;
    int pos = row & (Sc - 1);
    size_t base = (size_t)row * HS + h * HDc + d;
    float x1 = arr[base], x2 = arr[base + 64];
    float c  = cb[pos * HDc + d];
    float sn = sb[pos * HDc + d];
    arr[base]      = x1 * c - x2 * sn;
    arr[base + 64] = x2 * c + x1 * sn;
}

// ---------------------------------------------------------------------------
// Batched causal scores: S[bh] = scale * Q_bh * K_bh^T, masked entries -> 0
// grid = (ktile=16, qtile=16, bh=32); blocks with kt > qt exit immediately.
// ---------------------------------------------------------------------------
__global__ __launch_bounds__(256) void attn_scores(
    const float* __restrict__ Q, const float* __restrict__ Km,
    float* __restrict__ Scp)
{
    int kt = blockIdx.x, qt = blockIdx.y, bh = blockIdx.z;
    if (kt > qt) return;
    int b = bh >> 4, h = bh & 15;

    __shared__ uint32_t sA[128][36];
    __shared__ uint32_t sB[128][36];
    float acc[2][8][4];
#pragma unroll
    for (int mi = 0; mi < 2; mi++)
#pragma unroll
        for (int ni = 0; ni < 8; ni++)
#pragma unroll
            for (int j = 0; j < 4; j++) acc[mi][ni][j] = 0.f;

    const float* Ab = Q  + ((size_t)(b * Sc + qt * 128)) * HS + h * HDc;
    const float* Bb = Km + ((size_t)(b * Sc + kt * 128)) * HS + h * HDc;
    mainloop_tn(Ab, Bb, HS, HS, HDc, sA, sB, acc);

    float* C = Scp + (size_t)bh * Sc * Sc;
    const int tid = threadIdx.x, lane = tid & 31, warp = tid >> 5;
    const int g = lane >> 2, tg = lane & 3;
    const int wm = (warp & 3) * 32, wn = (warp >> 2) * 64;
#pragma unroll
    for (int mi = 0; mi < 2; mi++)
#pragma unroll
        for (int ni = 0; ni < 8; ni++) {
            int r0 = qt * 128 + wm + mi * 16 + g;
            int c0 = kt * 128 + wn + ni * 8 + tg * 2;
            float s0 = acc[mi][ni][0] * SCALE;
            float s1 = acc[mi][ni][1] * SCALE;
            float s2 = acc[mi][ni][2] * SCALE;
            float s3 = acc[mi][ni][3] * SCALE;
            C[(size_t)r0 * Sc + c0]           = (c0     <= r0    ) ? s0 : 0.f;
            C[(size_t)r0 * Sc + c0 + 1]       = (c0 + 1 <= r0    ) ? s1 : 0.f;
            C[(size_t)(r0 + 8) * Sc + c0]     = (c0     <= r0 + 8) ? s2 : 0.f;
            C[(size_t)(r0 + 8) * Sc + c0 + 1] = (c0 + 1 <= r0 + 8) ? s3 : 0.f;
        }
}

// ---------------------------------------------------------------------------
// Causal softmax in-place per row (only k <= q touched). grid = (S, BH)
// ---------------------------------------------------------------------------
__global__ __launch_bounds__(256) void softmax_kernel(float* __restrict__ Scp)
{
    int q = blockIdx.x, bh = blockIdx.y;
    float* row = Scp + (size_t)bh * Sc * Sc + (size_t)q * Sc;
    int n = q + 1;
    float m = -1e30f, s = 0.f;
    for (int k = threadIdx.x; k < n; k += 256) {
        float x = row[k];
        float mn = fmaxf(m, x);
        s = s * __expf(m - mn) + __expf(x - mn);
        m = mn;
    }
    __shared__ float sm[256], ss[256];
    sm[threadIdx.x] = m; ss[threadIdx.x] = s;
    __syncthreads();
    for (int off = 128; off; off >>= 1) {
        if (threadIdx.x < off) {
            float m2 = sm[threadIdx.x + off], s2 = ss[threadIdx.x + off];
            float mn = fmaxf(sm[threadIdx.x], m2);
            ss[threadIdx.x] = ss[threadIdx.x] * __expf(sm[threadIdx.x] - mn)
                            + s2 * __expf(m2 - mn);
            sm[threadIdx.x] = mn;
        }
        __syncthreads();
    }
    float M = sm[0];
    float inv = 1.f / ss[0];
    for (int k = threadIdx.x; k < n; k += 256)
        row[k] = __expf(row[k] - M) * inv;
}

// ---------------------------------------------------------------------------
// Batched PV: O_bh[128 x 128] tile = P(128 x kmax) * V_bh(kmax x 128)  (NN)
// grid = (qtile=16, bh=32); k-loop stops at diagonal (P is 0 above it).
// ---------------------------------------------------------------------------
__global__ __launch_bounds__(256) void attn_pv(
    const float* __restrict__ Scp, const float* __restrict__ V,
    float* __restrict__ O)
{
    int qt = blockIdx.x, bh = blockIdx.y;
    int b = bh >> 4, h = bh & 15;

    __shared__ uint32_t sA[128][36];
    __shared__ uint32_t sB[32][136];
    float acc[2][8][4];
#pragma unroll
    for (int mi = 0; mi < 2; mi++)
#pragma unroll
        for (int ni = 0; ni < 8; ni++)
#pragma unroll
            for (int j = 0; j < 4; j++) acc[mi][ni][j] = 0.f;

    const float* Ab = Scp + (size_t)bh * Sc * Sc + (size_t)qt * 128 * Sc;
    const float* Bv = V + ((size_t)(b * Sc)) * HS + h * HDc;

    const int tid  = threadIdx.x;
    const int lane = tid & 31, warp = tid >> 5;
    const int g = lane >> 2, tg = lane & 3;
    const int wm = (warp & 3) * 32, wn = (warp >> 2) * 64;
    const int lr = tid >> 3, lc = (tid & 7) * 4;
    const int kmax = (qt + 1) * 128;

    for (int k0 = 0; k0 < kmax; k0 += 32) {
#pragma unroll
        for (int i = 0; i < 4; i++) {
            int r = lr + i * 32;
            float4 va = *(const float4*)(Ab + (size_t)r * Sc + k0 + lc);
            sA[r][lc + 0] = f2t(va.x); sA[r][lc + 1] = f2t(va.y);
            sA[r][lc + 2] = f2t(va.z); sA[r][lc + 3] = f2t(va.w);
        }
#pragma unroll
        for (int i = 0; i < 4; i++) {
            int idx = tid + i * 256;           // 1024 float4 = 32 x 128 floats
            int kr  = idx >> 5;
            int c   = (idx & 31) * 4;
            float4 vb = *(const float4*)(Bv + (size_t)(k0 + kr) * HS + c);
            sB[kr][c + 0] = f2t(vb.x); sB[kr][c + 1] = f2t(vb.y);
            sB[kr][c + 2] = f2t(vb.z); sB[kr][c + 3] = f2t(vb.w);
        }
        __syncthreads();
#pragma unroll
        for (int ks = 0; ks < 4; ks++) {
            uint32_t af[2][4];
#pragma unroll
            for (int mi = 0; mi < 2; mi++) {
                int r = wm + mi * 16 + g, c = ks * 8 + tg;
                af[mi][0] = sA[r][c];     af[mi][1] = sA[r + 8][c];
                af[mi][2] = sA[r][c + 4]; af[mi][3] = sA[r + 8][c + 4];
            }
            uint32_t bf[8][2];
#pragma unroll
            for (int ni = 0; ni < 8; ni++) {
                int n = wn + ni * 8 + g;
                bf[ni][0] = sB[ks * 8 + tg][n];
                bf[ni][1] = sB[ks * 8 + tg + 4][n];
            }
#pragma unroll
            for (int mi = 0; mi < 2; mi++)
#pragma unroll
                for (int ni = 0; ni < 8; ni++)
                    mma8(acc[mi][ni], af[mi], bf[ni]);
        }
        __syncthreads();
    }

    float* Ob = O + ((size_t)(b * Sc + qt * 128)) * HS + h * HDc;
#pragma unroll
    for (int mi = 0; mi < 2; mi++)
#pragma unroll
        for (int ni = 0; ni < 8; ni++) {
            int r = wm + mi * 16 + g;
            int c = wn + ni * 8 + tg * 2;
            float2 v0; v0.x = acc[mi][ni][0]; v0.y = acc[mi][ni][1];
            float2 v1; v1.x = acc[mi][ni][2]; v1.y = acc[mi][ni][3];
            *(float2*)(Ob + (size_t)r * HS + c)       = v0;
            *(float2*)(Ob + (size_t)(r + 8) * HS + c) = v1;
        }
}

// ---------------------------------------------------------------------------
// Launcher
// ---------------------------------------------------------------------------
extern "C" void kernel_launch(void* const* d_in, const int* in_sizes, int n_in,
                              void* d_out, int out_size)
{
    const float* hs = (const float*)d_in[0];
    const float* wq = (const float*)d_in[1];
    const float* wk = (const float*)d_in[2];
    const float* wv = (const float*)d_in[3];
    const float* wo = (const float*)d_in[4];
    const float* cb = (const float*)d_in[5];
    const float* sb = (const float*)d_in[6];
    float* out = (float*)d_out;

    float *qp, *kp, *vp, *aop, *scp;
    cudaGetSymbolAddress((void**)&qp,  g_q);
    cudaGetSymbolAddress((void**)&kp,  g_k);
    cudaGetSymbolAddress((void**)&vp,  g_v);
    cudaGetSymbolAddress((void**)&aop, g_ao);
    cudaGetSymbolAddress((void**)&scp, g_sc);

    dim3 blk(256);
    dim3 gproj(HS / 128, MR / 128);                 // (16, 32)

    gemm_tn<<<gproj, blk>>>(hs, wq, qp, HS, HS, HS, HS);
    gemm_tn<<<gproj, blk>>>(hs, wk, kp, HS, HS, HS, HS);
    gemm_tn<<<gproj, blk>>>(hs, wv, vp, HS, HS, HS, HS);

    rope_kernel<<<dim3(MR * NHc * 64 / 256, 2), blk>>>(qp, kp, cb, sb);

    attn_scores<<<dim3(Sc / 128, Sc / 128, BHc), blk>>>(qp, kp, scp);
    softmax_kernel<<<dim3(Sc, BHc), blk>>>(scp);
    attn_pv<<<dim3(Sc / 128, BHc), blk>>>(scp, vp, aop);

    gemm_tn<<<gproj, blk>>>(aop, wo, out, HS, HS, HS, HS);
}

// round 2
// speedup vs baseline: 1.2693x; 1.2693x over previous
#include <cuda_runtime.h>
#include <cstdint>
#include <cstddef>

// Problem constants
constexpr int Bc  = 2;
constexpr int Sc  = 2048;
constexpr int HS  = 2048;
constexpr int NHc = 16;
constexpr int HDc = 128;
constexpr int MR  = Bc * Sc;    // 4096 rows of (b, s)
constexpr int BHc = Bc * NHc;   // 32 (batch*heads)
constexpr float SCALE = 0.08838834764831845f;  // 1/sqrt(128)

// Scratch (device globals — allocation-free per harness rules)
__device__ float g_q [MR * HS];
__device__ float g_k [MR * HS];
__device__ float g_v [MR * HS];
__device__ float g_ao[MR * HS];

// ---------------------------------------------------------------------------
// TF32 helpers
// ---------------------------------------------------------------------------
__device__ __forceinline__ uint32_t f2t(float x) {
    uint32_t r;
    asm("cvt.rna.tf32.f32 %0, %1;" : "=r"(r) : "f"(x));
    return r;
}

__device__ __forceinline__ void mma8(float* c, const uint32_t* a, const uint32_t* b) {
    asm volatile(
        "mma.sync.aligned.m16n8k8.row.col.f32.tf32.tf32.f32 "
        "{%0,%1,%2,%3},{%4,%5,%6,%7},{%8,%9},{%0,%1,%2,%3};\n"
        : "+f"(c[0]), "+f"(c[1]), "+f"(c[2]), "+f"(c[3])
        : "r"(a[0]), "r"(a[1]), "r"(a[2]), "r"(a[3]),
          "r"(b[0]), "r"(b[1]));
}

// Compute one 32-deep k-chunk: acc += A(128x32) * B(128x32)^T, [36]-stride bufs
__device__ __forceinline__ void mma_tile_tn(
    const uint32_t (*cA)[36], const uint32_t (*cB)[36],
    float (&acc)[2][8][4], int wm, int wn, int g, int tg)
{
#pragma unroll
    for (int ks = 0; ks < 4; ks++) {
        uint32_t af[2][4];
#pragma unroll
        for (int mi = 0; mi < 2; mi++) {
            int r = wm + mi * 16 + g, c = ks * 8 + tg;
            af[mi][0] = cA[r][c];     af[mi][1] = cA[r + 8][c];
            af[mi][2] = cA[r][c + 4]; af[mi][3] = cA[r + 8][c + 4];
        }
        uint32_t bf[8][2];
#pragma unroll
        for (int ni = 0; ni < 8; ni++) {
            int n = wn + ni * 8 + g, c = ks * 8 + tg;
            bf[ni][0] = cB[n][c]; bf[ni][1] = cB[n][c + 4];
        }
#pragma unroll
        for (int mi = 0; mi < 2; mi++)
#pragma unroll
            for (int ni = 0; ni < 8; ni++)
                mma8(acc[mi][ni], af[mi], bf[ni]);
    }
}

// ---------------------------------------------------------------------------
// Pipelined projection GEMM: C[M,N] = A[M,K] * B[N,K]^T (row-major)
// Double-buffered smem + register prefetch of next k-chunk.
// grid = (N/128, M/128), block = 256, dyn smem = 73728 B
// ---------------------------------------------------------------------------
__global__ __launch_bounds__(256) void gemm_tn(
    const float* __restrict__ A, const float* __restrict__ B,
    float* __restrict__ C, int lda, int ldb, int ldc, int K)
{
    extern __shared__ uint32_t dynsmem[];
    uint32_t (*sA)[36] = (uint32_t(*)[36])dynsmem;                    // [2][128][36]
    uint32_t (*sB)[36] = (uint32_t(*)[36])(dynsmem + 2 * 128 * 36);   // [2][128][36]

    const int tid  = threadIdx.x;
    const int lane = tid & 31, warp = tid >> 5;
    const int g = lane >> 2, tg = lane & 3;
    const int wm = (warp & 3) * 32, wn = (warp >> 2) * 64;
    const int lr = tid >> 3, lc = (tid & 7) * 4;

    const float* Ab = A + (size_t)blockIdx.y * 128 * lda;
    const float* Bb = B + (size_t)blockIdx.x * 128 * ldb;

    float acc[2][8][4];
#pragma unroll
    for (int mi = 0; mi < 2; mi++)
#pragma unroll
        for (int ni = 0; ni < 8; ni++)
#pragma unroll
            for (int j = 0; j < 4; j++) acc[mi][ni][j] = 0.f;

    float4 pa[4], pb[4];
#pragma unroll
    for (int i = 0; i < 4; i++) {
        pa[i] = *(const float4*)(Ab + (size_t)(lr + i * 32) * lda + lc);
        pb[i] = *(const float4*)(Bb + (size_t)(lr + i * 32) * ldb + lc);
    }
#pragma unroll
    for (int i = 0; i < 4; i++) {
        int r = lr + i * 32;
        sA[r][lc] = f2t(pa[i].x); sA[r][lc + 1] = f2t(pa[i].y);
        sA[r][lc + 2] = f2t(pa[i].z); sA[r][lc + 3] = f2t(pa[i].w);
        sB[r][lc] = f2t(pb[i].x); sB[r][lc + 1] = f2t(pb[i].y);
        sB[r][lc + 2] = f2t(pb[i].z); sB[r][lc + 3] = f2t(pb[i].w);
    }
    __syncthreads();

    const int nchunk = K / 32;
    for (int ck = 0; ck < nchunk; ck++) {
        const int buf = ck & 1;
        const bool more = (ck + 1 < nchunk);
        if (more) {
            const int k1 = (ck + 1) * 32;
#pragma unroll
            for (int i = 0; i < 4; i++) {
                pa[i] = *(const float4*)(Ab + (size_t)(lr + i * 32) * lda + k1 + lc);
                pb[i] = *(const float4*)(Bb + (size_t)(lr + i * 32) * ldb + k1 + lc);
            }
        }
        mma_tile_tn(sA + buf * 128, sB + buf * 128, acc, wm, wn, g, tg);
        if (more) {
            const int nb = (buf ^ 1) * 128;
#pragma unroll
            for (int i = 0; i < 4; i++) {
                int r = nb + lr + i * 32;
                sA[r][lc] = f2t(pa[i].x); sA[r][lc + 1] = f2t(pa[i].y);
                sA[r][lc + 2] = f2t(pa[i].z); sA[r][lc + 3] = f2t(pa[i].w);
                sB[r][lc] = f2t(pb[i].x); sB[r][lc + 1] = f2t(pb[i].y);
                sB[r][lc + 2] = f2t(pb[i].z); sB[r][lc + 3] = f2t(pb[i].w);
            }
        }
        __syncthreads();
    }

    const size_t rbase = (size_t)blockIdx.y * 128;
    const int cbase = blockIdx.x * 128;
#pragma unroll
    for (int mi = 0; mi < 2; mi++)
#pragma unroll
        for (int ni = 0; ni < 8; ni++) {
            size_t r = rbase + wm + mi * 16 + g;
            int    c = cbase + wn + ni * 8 + tg * 2;
            float2 v0; v0.x = acc[mi][ni][0]; v0.y = acc[mi][ni][1];
            float2 v1; v1.x = acc[mi][ni][2]; v1.y = acc[mi][ni][3];
            *(float2*)(C + r * ldc + c)       = v0;
            *(float2*)(C + (r + 8) * ldc + c) = v1;
        }
}

// ---------------------------------------------------------------------------
// RoPE (in place on Q and K). grid = (MR*NH*64/256, 2), blockIdx.y: 0=Q 1=K
// ---------------------------------------------------------------------------
__global__ __launch_bounds__(256) void rope_kernel(
    float* __restrict__ q, float* __restrict__ k,
    const float* __restrict__ cb, const float* __restrict__ sb)
{
    int i = blockIdx.x * 256 + threadIdx.x;
    float* arr = blockIdx.y ? k : q;
    int d   = i & 63;
    int h   = (i >> 6) & (NHc - 1);
    int row = i >> 10;
    int pos = row & (Sc - 1);
    size_t base = (size_t)row * HS + h * HDc + d;
    float x1 = arr[base], x2 = arr[base + 64];
    float c  = cb[pos * HDc + d];
    float sn = sb[pos * HDc + d];
    arr[base]      = x1 * c - x2 * sn;
    arr[base + 64] = x2 * c + x1 * sn;
}

// ---------------------------------------------------------------------------
// Fused causal flash attention.
//   grid = (16, 32) -> (qt reversed big-first, bh), block = 256
//   smem: sQ[128][132] | sKS[128][132] (K tile, then aliased as P tile)
//         sV[128][136] | sRM[128][2] | sRS[128][2]          = 206848 B
// ---------------------------------------------------------------------------
constexpr int FL_Q  = 0;
constexpr int FL_KS = 128 * 132;
constexpr int FL_V  = FL_KS + 128 * 132;
constexpr int FL_RM = FL_V + 128 * 136;
constexpr int FL_RS = FL_RM + 128 * 2;
constexpr int FL_SMEM_BYTES = (FL_RS + 128 * 2) * 4;

__global__ __launch_bounds__(256) void flash_attn(
    const float* __restrict__ Q, const float* __restrict__ K,
    const float* __restrict__ V, float* __restrict__ O)
{
    extern __shared__ uint32_t sm[];
    uint32_t (*sQ)[132]  = (uint32_t(*)[132])(sm + FL_Q);
    uint32_t (*sKS)[132] = (uint32_t(*)[132])(sm + FL_KS);
    uint32_t (*sV)[136]  = (uint32_t(*)[136])(sm + FL_V);
    float    (*sRM)[2]   = (float(*)[2])(sm + FL_RM);
    float    (*sRS)[2]   = (float(*)[2])(sm + FL_RS);

    const int qt = (int)gridDim.x - 1 - (int)blockIdx.x;   // big blocks first
    const int bh = blockIdx.y;
    const int b = bh >> 4, h = bh & 15;
    const int tid  = threadIdx.x;
    const int lane = tid & 31, warp = tid >> 5;
    const int g = lane >> 2, tg = lane & 3;
    const int wm = (warp & 3) * 32, wn = (warp >> 2) * 64;
    const int wp = warp >> 2;                              // warp-pair id (n-half)

    // Load Q tile once (tf32)
    const float* Qb = Q + (size_t)(b * Sc + qt * 128) * HS + h * HDc;
    for (int i = tid; i < 128 * 32; i += 256) {
        int r = i >> 5, c = (i & 31) * 4;
        float4 v = *(const float4*)(Qb + (size_t)r * HS + c);
        sQ[r][c] = f2t(v.x); sQ[r][c + 1] = f2t(v.y);
        sQ[r][c + 2] = f2t(v.z); sQ[r][c + 3] = f2t(v.w);
    }

    float acc_o[2][8][4];
#pragma unroll
    for (int mi = 0; mi < 2; mi++)
#pragma unroll
        for (int ni = 0; ni < 8; ni++)
#pragma unroll
            for (int j = 0; j < 4; j++) acc_o[mi][ni][j] = 0.f;
    float m_r[4], l_r[4];
#pragma unroll
    for (int j = 0; j < 4; j++) { m_r[j] = -1e30f; l_r[j] = 0.f; }

    for (int kt = 0; kt <= qt; kt++) {
        const float* Kb = K + (size_t)(b * Sc + kt * 128) * HS + h * HDc;
        const float* Vb = V + (size_t)(b * Sc + kt * 128) * HS + h * HDc;

        __syncthreads();   // prior PV reads of sKS / sV done; Q visible (iter 0)
        for (int i = tid; i < 128 * 32; i += 256) {
            int r = i >> 5, c = (i & 31) * 4;
            float4 v = *(const float4*)(Kb + (size_t)r * HS + c);
            sKS[r][c] = f2t(v.x); sKS[r][c + 1] = f2t(v.y);
            sKS[r][c + 2] = f2t(v.z); sKS[r][c + 3] = f2t(v.w);
            float4 w = *(const float4*)(Vb + (size_t)r * HS + c);
            sV[r][c] = f2t(w.x); sV[r][c + 1] = f2t(w.y);
            sV[r][c + 2] = f2t(w.z); sV[r][c + 3] = f2t(w.w);
        }
        __syncthreads();

        // ---- S = Q * K^T (TN over full HD=128 depth) ----
        float accs[2][8][4];
#pragma unroll
        for (int mi = 0; mi < 2; mi++)
#pragma unroll
            for (int ni = 0; ni < 8; ni++)
#pragma unroll
                for (int j = 0; j < 4; j++) accs[mi][ni][j] = 0.f;

#pragma unroll
        for (int ks = 0; ks < 16; ks++) {
            uint32_t af[2][4];
#pragma unroll
            for (int mi = 0; mi < 2; mi++) {
                int r = wm + mi * 16 + g, c = ks * 8 + tg;
                af[mi][0] = sQ[r][c];     af[mi][1] = sQ[r + 8][c];
                af[mi][2] = sQ[r][c + 4]; af[mi][3] = sQ[r + 8][c + 4];
            }
            uint32_t bf[8][2];
#pragma unroll
            for (int ni = 0; ni < 8; ni++) {
                int n = wn + ni * 8 + g, c = ks * 8 + tg;
                bf[ni][0] = sKS[n][c]; bf[ni][1] = sKS[n][c + 4];
            }
#pragma unroll
            for (int mi = 0; mi < 2; mi++)
#pragma unroll
                for (int ni = 0; ni < 8; ni++)
                    mma8(accs[mi][ni], af[mi], bf[ni]);
        }

        // ---- scale + causal mask (diagonal tile only) ----
        const bool diag = (kt == qt);
#pragma unroll
        for (int mi = 0; mi < 2; mi++)
#pragma unroll
            for (int ni = 0; ni < 8; ni++) {
                int r0 = wm + mi * 16 + g, r1 = r0 + 8;
                int c0 = wn + ni * 8 + tg * 2, c1 = c0 + 1;
                accs[mi][ni][0] *= SCALE; accs[mi][ni][1] *= SCALE;
                accs[mi][ni][2] *= SCALE; accs[mi][ni][3] *= SCALE;
                if (diag) {
                    if (c0 > r0) accs[mi][ni][0] = -1e30f;
                    if (c1 > r0) accs[mi][ni][1] = -1e30f;
                    if (c0 > r1) accs[mi][ni][2] = -1e30f;
                    if (c1 > r1) accs[mi][ni][3] = -1e30f;
                }
            }

        // ---- row max: local -> quad shuffle -> cross warp-pair via smem ----
        float lm[4];
#pragma unroll
        for (int j = 0; j < 4; j++) lm[j] = -1e30f;
#pragma unroll
        for (int mi = 0; mi < 2; mi++)
#pragma unroll
            for (int ni = 0; ni < 8; ni++) {
                lm[mi * 2]     = fmaxf(lm[mi * 2],     fmaxf(accs[mi][ni][0], accs[mi][ni][1]));
                lm[mi * 2 + 1] = fmaxf(lm[mi * 2 + 1], fmaxf(accs[mi][ni][2], accs[mi][ni][3]));
            }
#pragma unroll
        for (int off = 1; off <= 2; off <<= 1)
#pragma unroll
            for (int j = 0; j < 4; j++)
                lm[j] = fmaxf(lm[j], __shfl_xor_sync(0xffffffffu, lm[j], off));
        if (tg == 0) {
#pragma unroll
            for (int j = 0; j < 4; j++) {
                int rloc = wm + (j >> 1) * 16 + g + (j & 1) * 8;
                sRM[rloc][wp] = lm[j];
            }
        }
        __syncthreads();

        // ---- softmax update: m, correction, p = exp(s-m), rescale acc_o ----
        float rsum[4];
#pragma unroll
        for (int j = 0; j < 4; j++) {
            int rloc = wm + (j >> 1) * 16 + g + (j & 1) * 8;
            float tmax = fmaxf(sRM[rloc][0], sRM[rloc][1]);
            float mnew = fmaxf(m_r[j], tmax);
            float corr = __expf(m_r[j] - mnew);
            m_r[j] = mnew;
            l_r[j] *= corr;
            int mi = j >> 1, s0 = (j & 1) * 2;
            float lsum = 0.f;
#pragma unroll
            for (int ni = 0; ni < 8; ni++) {
                acc_o[mi][ni][s0]     *= corr;
                acc_o[mi][ni][s0 + 1] *= corr;
                float p0 = __expf(accs[mi][ni][s0]     - mnew);
                float p1 = __expf(accs[mi][ni][s0 + 1] - mnew);
                accs[mi][ni][s0] = p0; accs[mi][ni][s0 + 1] = p1;
                lsum += p0 + p1;
            }
            rsum[j] = lsum;
        }
#pragma unroll
        for (int off = 1; off <= 2; off <<= 1)
#pragma unroll
            for (int j = 0; j < 4; j++)
                rsum[j] += __shfl_xor_sync(0xffffffffu, rsum[j], off);
        if (tg == 0) {
#pragma unroll
            for (int j = 0; j < 4; j++) {
                int rloc = wm + (j >> 1) * 16 + g + (j & 1) * 8;
                sRS[rloc][wp] = rsum[j];
            }
        }

        // ---- write P (tf32) into the K-alias region ----
#pragma unroll
        for (int mi = 0; mi < 2; mi++)
#pragma unroll
            for (int ni = 0; ni < 8; ni++) {
                int r0 = wm + mi * 16 + g, c0 = wn + ni * 8 + tg * 2;
                sKS[r0][c0]     = f2t(accs[mi][ni][0]);
                sKS[r0][c0 + 1] = f2t(accs[mi][ni][1]);
                sKS[r0 + 8][c0]     = f2t(accs[mi][ni][2]);
                sKS[r0 + 8][c0 + 1] = f2t(accs[mi][ni][3]);
            }
        __syncthreads();

#pragma unroll
        for (int j = 0; j < 4; j++) {
            int rloc = wm + (j >> 1) * 16 + g + (j & 1) * 8;
            l_r[j] += sRS[rloc][0] + sRS[rloc][1];
        }

        // ---- acc_o += P(128x128) * V(128x128)  (NN) ----
#pragma unroll
        for (int ks = 0; ks < 16; ks++) {
            uint32_t af[2][4];
#pragma unroll
            for (int mi = 0; mi < 2; mi++) {
                int r = wm + mi * 16 + g, c = ks * 8 + tg;
                af[mi][0] = sKS[r][c];     af[mi][1] = sKS[r + 8][c];
                af[mi][2] = sKS[r][c + 4]; af[mi][3] = sKS[r + 8][c + 4];
            }
            uint32_t bf[8][2];
#pragma unroll
            for (int ni = 0; ni < 8; ni++) {
                int n = wn + ni * 8 + g;
                bf[ni][0] = sV[ks * 8 + tg][n];
                bf[ni][1] = sV[ks * 8 + tg + 4][n];
            }
#pragma unroll
            for (int mi = 0; mi < 2; mi++)
#pragma unroll
                for (int ni = 0; ni < 8; ni++)
                    mma8(acc_o[mi][ni], af[mi], bf[ni]);
        }
    }

    // ---- epilogue: O = acc_o / l ----
    float* Ob = O + (size_t)(b * Sc + qt * 128) * HS + h * HDc;
#pragma unroll
    for (int mi = 0; mi < 2; mi++) {
        float inv0 = 1.f / l_r[mi * 2];
        float inv1 = 1.f / l_r[mi * 2 + 1];
#pragma unroll
        for (int ni = 0; ni < 8; ni++) {
            int r = wm + mi * 16 + g;
            int c = wn + ni * 8 + tg * 2;
            float2 v0; v0.x = acc_o[mi][ni][0] * inv0; v0.y = acc_o[mi][ni][1] * inv0;
            float2 v1; v1.x = acc_o[mi][ni][2] * inv1; v1.y = acc_o[mi][ni][3] * inv1;
            *(float2*)(Ob + (size_t)r * HS + c)       = v0;
            *(float2*)(Ob + (size_t)(r + 8) * HS + c) = v1;
        }
    }
}

// ---------------------------------------------------------------------------
// Launcher
// ---------------------------------------------------------------------------
extern "C" void kernel_launch(void* const* d_in, const int* in_sizes, int n_in,
                              void* d_out, int out_size)
{
    const float* hs = (const float*)d_in[0];
    const float* wq = (const float*)d_in[1];
    const float* wk = (const float*)d_in[2];
    const float* wv = (const float*)d_in[3];
    const float* wo = (const float*)d_in[4];
    const float* cb = (const float*)d_in[5];
    const float* sb = (const float*)d_in[6];
    float* out = (float*)d_out;

    float *qp, *kp, *vp, *aop;
    cudaGetSymbolAddress((void**)&qp,  g_q);
    cudaGetSymbolAddress((void**)&kp,  g_k);
    cudaGetSymbolAddress((void**)&vp,  g_v);
    cudaGetSymbolAddress((void**)&aop, g_ao);

    constexpr int GEMM_SMEM = 2 * 2 * 128 * 36 * 4;   // 73728 B
    cudaFuncSetAttribute(gemm_tn, cudaFuncAttributeMaxDynamicSharedMemorySize, GEMM_SMEM);
    cudaFuncSetAttribute(flash_attn, cudaFuncAttributeMaxDynamicSharedMemorySize, FL_SMEM_BYTES);

    dim3 blk(256);
    dim3 gproj(HS / 128, MR / 128);                 // (16, 32)

    gemm_tn<<<gproj, blk, GEMM_SMEM>>>(hs, wq, qp, HS, HS, HS, HS);
    gemm_tn<<<gproj, blk, GEMM_SMEM>>>(hs, wk, kp, HS, HS, HS, HS);
    gemm_tn<<<gproj, blk, GEMM_SMEM>>>(hs, wv, vp, HS, HS, HS, HS);

    rope_kernel<<<dim3(MR * NHc * 64 / 256, 2), blk>>>(qp, kp, cb, sb);

    flash_attn<<<dim3(Sc / 128, BHc), blk, FL_SMEM_BYTES>>>(qp, kp, vp, aop);

    gemm_tn<<<gproj, blk, GEMM_SMEM>>>(aop, wo, out, HS, HS, HS, HS);
}

// round 5
// speedup vs baseline: 1.3375x; 1.0537x over previous
#include <cuda_runtime.h>
#include <cstdint>
#include <cstddef>

// Problem constants
constexpr int Bc  = 2;
constexpr int Sc  = 2048;
constexpr int HS  = 2048;
constexpr int NHc = 16;
constexpr int HDc = 128;
constexpr int MR  = Bc * Sc;    // 4096 rows of (b, s)
constexpr int BHc = Bc * NHc;   // 32 (batch*heads)
constexpr float SCALE = 0.08838834764831845f;  // 1/sqrt(128)

// Scratch (device globals — allocation-free per harness rules)
__device__ float g_q [MR * HS];
__device__ float g_k [MR * HS];
__device__ float g_v [MR * HS];
__device__ float g_ao[MR * HS];
__device__ float g_hs[MR * HS];     // pre-rounded hidden states
__device__ float g_wq[HS * HS];     // pre-rounded weights
__device__ float g_wk[HS * HS];
__device__ float g_wv[HS * HS];
__device__ float g_wo[HS * HS];

// ---------------------------------------------------------------------------
// Helpers
// ---------------------------------------------------------------------------
__device__ __forceinline__ uint32_t f2t(float x) {
    uint32_t r;
    asm("cvt.rna.tf32.f32 %0, %1;" : "=r"(r) : "f"(x));
    return r;
}
__device__ __forceinline__ float f2tf(float x) { return __uint_as_float(f2t(x)); }

__device__ __forceinline__ uint32_t smem_u32(const void* p) {
    uint32_t a;
    asm("{ .reg .u64 t; cvta.to.shared.u64 t, %1; cvt.u32.u64 %0, t; }"
        : "=r"(a) : "l"(p));
    return a;
}

__device__ __forceinline__ void cpa16(uint32_t dst, const void* src) {
    asm volatile("cp.async.cg.shared.global [%0], [%1], 16;"
                 :: "r"(dst), "l"(src) : "memory");
}
__device__ __forceinline__ void cpa_commit() {
    asm volatile("cp.async.commit_group;" ::: "memory");
}
template <int N>
__device__ __forceinline__ void cpa_wait() {
    asm volatile("cp.async.wait_group %0;" :: "n"(N) : "memory");
}

__device__ __forceinline__ void mma8(float* c, const uint32_t* a, const uint32_t* b) {
    asm volatile(
        "mma.sync.aligned.m16n8k8.row.col.f32.tf32.tf32.f32 "
        "{%0,%1,%2,%3},{%4,%5,%6,%7},{%8,%9},{%0,%1,%2,%3};\n"
        : "+f"(c[0]), "+f"(c[1]), "+f"(c[2]), "+f"(c[3])
        : "r"(a[0]), "r"(a[1]), "r"(a[2]), "r"(a[3]),
          "r"(b[0]), "r"(b[1]));
}

// ---------------------------------------------------------------------------
// Elementwise tf32 rounding pass: out[i] = rna(in[i])
// ---------------------------------------------------------------------------
__global__ __launch_bounds__(256) void round_tf32(
    const float4* __restrict__ in, float4* __restrict__ out, int n4)
{
    int i = blockIdx.x * 256 + threadIdx.x;
    if (i < n4) {
        float4 v = in[i];
        v.x = f2tf(v.x); v.y = f2tf(v.y); v.z = f2tf(v.z); v.w = f2tf(v.w);
        out[i] = v;
    }
}

// ---------------------------------------------------------------------------
// Pipelined TN GEMM on pre-rounded tf32 data (bit patterns in fp32 arrays):
//   C[M,N] = A[M,K] * B[N,K]^T     (row-major)
// BK=64, 3-stage cp.async ring. grid = (N/128, M/128), block = 256.
// smem per stage: A 128x68 + B 128x68 floats = 69632 B; 3 stages = 208896 B.
// ---------------------------------------------------------------------------
constexpr int G_STRIDE = 68;                         // floats per smem row
constexpr int G_OP_BYTES = 128 * G_STRIDE * 4;       // 34816
constexpr int G_STAGE_BYTES = 2 * G_OP_BYTES;        // 69632
constexpr int G_STAGES = 3;
constexpr int G_SMEM = G_STAGES * G_STAGE_BYTES;     // 208896

__global__ __launch_bounds__(256) void gemm_tc(
    const float* __restrict__ A, const float* __restrict__ B,
    float* __restrict__ C, int lda, int ldb, int ldc, int K, int roundOut)
{
    extern __shared__ char dsm[];
    const uint32_t sbase = smem_u32(dsm);

    const int tid  = threadIdx.x;
    const int lane = tid & 31, warp = tid >> 5;
    const int g = lane >> 2, tg = lane & 3;
    const int wm = (warp & 3) * 32, wn = (warp >> 2) * 64;
    const int lrow = tid >> 4;         // 0..15
    const int lq   = tid & 15;         // 16B unit within 64-float row

    const float* Ab = A + (size_t)blockIdx.y * 128 * lda;
    const float* Bb = B + (size_t)blockIdx.x * 128 * ldb;

    float acc[2][8][4];
#pragma unroll
    for (int mi = 0; mi < 2; mi++)
#pragma unroll
        for (int ni = 0; ni < 8; ni++)
#pragma unroll
            for (int j = 0; j < 4; j++) acc[mi][ni][j] = 0.f;

    auto issue_stage = [&](int s, int k0) {
        const uint32_t stA = sbase + s * G_STAGE_BYTES;
        const uint32_t stB = stA + G_OP_BYTES;
#pragma unroll
        for (int i = 0; i < 8; i++) {
            int r = lrow + i * 16;
            cpa16(stA + r * (G_STRIDE * 4) + lq * 16,
                  Ab + (size_t)r * lda + k0 + lq * 4);
            cpa16(stB + r * (G_STRIDE * 4) + lq * 16,
                  Bb + (size_t)r * ldb + k0 + lq * 4);
        }
        cpa_commit();
    };

    const int nchunk = K / 64;         // 32
    issue_stage(0, 0);
    issue_stage(1, 64);
    issue_stage(2, 128);

    for (int c = 0; c < nchunk; c++) {
        cpa_wait<2>();
        __syncthreads();

        const int s = c % G_STAGES;
        const uint32_t (*sA)[G_STRIDE] =
            (const uint32_t(*)[G_STRIDE])(dsm + s * G_STAGE_BYTES);
        const uint32_t (*sB)[G_STRIDE] =
            (const uint32_t(*)[G_STRIDE])(dsm + s * G_STAGE_BYTES + G_OP_BYTES);

#pragma unroll
        for (int ks = 0; ks < 8; ks++) {
            uint32_t af[2][4];
#pragma unroll
            for (int mi = 0; mi < 2; mi++) {
                int r = wm + mi * 16 + g, cc = ks * 8 + tg;
                af[mi][0] = sA[r][cc];     af[mi][1] = sA[r + 8][cc];
                af[mi][2] = sA[r][cc + 4]; af[mi][3] = sA[r + 8][cc + 4];
            }
            uint32_t bf[8][2];
#pragma unroll
            for (int ni = 0; ni < 8; ni++) {
                int n = wn + ni * 8 + g, cc = ks * 8 + tg;
                bf[ni][0] = sB[n][cc]; bf[ni][1] = sB[n][cc + 4];
            }
#pragma unroll
            for (int mi = 0; mi < 2; mi++)
#pragma unroll
                for (int ni = 0; ni < 8; ni++)
                    mma8(acc[mi][ni], af[mi], bf[ni]);
        }
        __syncthreads();

        if (c + 3 < nchunk) issue_stage(s, (c + 3) * 64);
        else                cpa_commit();     // keep group count uniform
    }

    const size_t rbase = (size_t)blockIdx.y * 128;
    const int cbase = blockIdx.x * 128;
#pragma unroll
    for (int mi = 0; mi < 2; mi++)
#pragma unroll
        for (int ni = 0; ni < 8; ni++) {
            size_t r = rbase + wm + mi * 16 + g;
            int    cc = cbase + wn + ni * 8 + tg * 2;
            float2 v0, v1;
            if (roundOut) {
                v0.x = f2tf(acc[mi][ni][0]); v0.y = f2tf(acc[mi][ni][1]);
                v1.x = f2tf(acc[mi][ni][2]); v1.y = f2tf(acc[mi][ni][3]);
            } else {
                v0.x = acc[mi][ni][0]; v0.y = acc[mi][ni][1];
                v1.x = acc[mi][ni][2]; v1.y = acc[mi][ni][3];
            }
            *(float2*)(C + r * ldc + cc)       = v0;
            *(float2*)(C + (r + 8) * ldc + cc) = v1;
        }
}

// ---------------------------------------------------------------------------
// RoPE (in place on Q and K), writes tf32-pre-rounded values.
// grid = (MR*NH*64/256, 2), blockIdx.y: 0=Q 1=K
// ---------------------------------------------------------------------------
__global__ __launch_bounds__(256) void rope_kernel(
    float* __restrict__ q, float* __restrict__ k,
    const float* __restrict__ cb, const float* __restrict__ sb)
{
    int i = blockIdx.x * 256 + threadIdx.x;
    float* arr = blockIdx.y ? k : q;
    int d   = i & 63;
    int h   = (i >> 6) & (NHc - 1);
    int row = i >> 10;
    int pos = row & (Sc - 1);
    size_t base = (size_t)row * HS + h * HDc + d;
    float x1 = arr[base], x2 = arr[base + 64];
    float c  = cb[pos * HDc + d];
    float sn = sb[pos * HDc + d];
    arr[base]      = f2tf(x1 * c - x2 * sn);
    arr[base + 64] = f2tf(x2 * c + x1 * sn);
}

// ---------------------------------------------------------------------------
// Fused causal flash attention on pre-rounded Q/K/V; cp.async fills,
// V load overlapped with S-gemm + softmax. Writes pre-rounded ao.
//   grid = (16, 32) -> (qt reversed big-first, bh), block = 256
// ---------------------------------------------------------------------------
constexpr int FL_Q  = 0;
constexpr int FL_KS = 128 * 132;
constexpr int FL_V  = FL_KS + 128 * 132;
constexpr int FL_RM = FL_V + 128 * 136;
constexpr int FL_RS = FL_RM + 128 * 2;
constexpr int FL_SMEM_BYTES = (FL_RS + 128 * 2) * 4;

__global__ __launch_bounds__(256) void flash_attn(
    const float* __restrict__ Q, const float* __restrict__ K,
    const float* __restrict__ V, float* __restrict__ O)
{
    extern __shared__ uint32_t sm[];
    uint32_t (*sQ)[132]  = (uint32_t(*)[132])(sm + FL_Q);
    uint32_t (*sKS)[132] = (uint32_t(*)[132])(sm + FL_KS);
    uint32_t (*sV)[136]  = (uint32_t(*)[136])(sm + FL_V);
    float    (*sRM)[2]   = (float(*)[2])(sm + FL_RM);
    float    (*sRS)[2]   = (float(*)[2])(sm + FL_RS);
    const uint32_t sbase = smem_u32(sm);
    const uint32_t aQ  = sbase + FL_Q  * 4;
    const uint32_t aKS = sbase + FL_KS * 4;
    const uint32_t aV  = sbase + FL_V  * 4;

    const int qt = (int)gridDim.x - 1 - (int)blockIdx.x;
    const int bh = blockIdx.y;
    const int b = bh >> 4, h = bh & 15;
    const int tid  = threadIdx.x;
    const int lane = tid & 31, warp = tid >> 5;
    const int g = lane >> 2, tg = lane & 3;
    const int wm = (warp & 3) * 32, wn = (warp >> 2) * 64;
    const int wp = warp >> 2;

    // Q tile: 128 rows x 128 floats = 4096 16B units; 16 per thread
    const float* Qb = Q + (size_t)(b * Sc + qt * 128) * HS + h * HDc;
    {
#pragma unroll
        for (int i = 0; i < 16; i++) {
            int u = tid + i * 256;           // 0..4095
            int r = u >> 5, q = u & 31;      // row 0..127, 16B-unit 0..31
            cpa16(aQ + r * 528 + q * 16, Qb + (size_t)r * HS + q * 4);
        }
        cpa_commit();
    }

    float acc_o[2][8][4];
#pragma unroll
    for (int mi = 0; mi < 2; mi++)
#pragma unroll
        for (int ni = 0; ni < 8; ni++)
#pragma unroll
            for (int j = 0; j < 4; j++) acc_o[mi][ni][j] = 0.f;
    float m_r[4], l_r[4];
#pragma unroll
    for (int j = 0; j < 4; j++) { m_r[j] = -1e30f; l_r[j] = 0.f; }

    for (int kt = 0; kt <= qt; kt++) {
        const float* Kb = K + (size_t)(b * Sc + kt * 128) * HS + h * HDc;
        const float* Vb = V + (size_t)(b * Sc + kt * 128) * HS + h * HDc;

        __syncthreads();   // prior PV reads of sKS / sV complete
#pragma unroll
        for (int i = 0; i < 16; i++) {
            int u = tid + i * 256;
            int r = u >> 5, q = u & 31;
            cpa16(aKS + r * 528 + q * 16, Kb + (size_t)r * HS + q * 4);
        }
        cpa_commit();
#pragma unroll
        for (int i = 0; i < 16; i++) {
            int u = tid + i * 256;
            int r = u >> 5, q = u & 31;
            cpa16(aV + r * 544 + q * 16, Vb + (size_t)r * HS + q * 4);
        }
        cpa_commit();

        cpa_wait<1>();     // Q (first iter) + K complete; V may be in flight
        __syncthreads();

        // ---- S = Q * K^T ----
        float accs[2][8][4];
#pragma unroll
        for (int mi = 0; mi < 2; mi++)
#pragma unroll
            for (int ni = 0; ni < 8; ni++)
#pragma unroll
                for (int j = 0; j < 4; j++) accs[mi][ni][j] = 0.f;

#pragma unroll
        for (int ks = 0; ks < 16; ks++) {
            uint32_t af[2][4];
#pragma unroll
            for (int mi = 0; mi < 2; mi++) {
                int r = wm + mi * 16 + g, c = ks * 8 + tg;
                af[mi][0] = sQ[r][c];     af[mi][1] = sQ[r + 8][c];
                af[mi][2] = sQ[r][c + 4]; af[mi][3] = sQ[r + 8][c + 4];
            }
            uint32_t bf[8][2];
#pragma unroll
            for (int ni = 0; ni < 8; ni++) {
                int n = wn + ni * 8 + g, c = ks * 8 + tg;
                bf[ni][0] = sKS[n][c]; bf[ni][1] = sKS[n][c + 4];
            }
#pragma unroll
            for (int mi = 0; mi < 2; mi++)
#pragma unroll
                for (int ni = 0; ni < 8; ni++)
                    mma8(accs[mi][ni], af[mi], bf[ni]);
        }

        const bool diag = (kt == qt);
#pragma unroll
        for (int mi = 0; mi < 2; mi++)
#pragma unroll
            for (int ni = 0; ni < 8; ni++) {
                int r0 = wm + mi * 16 + g, r1 = r0 + 8;
                int c0 = wn + ni * 8 + tg * 2, c1 = c0 + 1;
                accs[mi][ni][0] *= SCALE; accs[mi][ni][1] *= SCALE;
                accs[mi][ni][2] *= SCALE; accs[mi][ni][3] *= SCALE;
                if (diag) {
                    if (c0 > r0) accs[mi][ni][0] = -1e30f;
                    if (c1 > r0) accs[mi][ni][1] = -1e30f;
                    if (c0 > r1) accs[mi][ni][2] = -1e30f;
                    if (c1 > r1) accs[mi][ni][3] = -1e30f;
                }
            }

        float lm[4];
#pragma unroll
        for (int j = 0; j < 4; j++) lm[j] = -1e30f;
#pragma unroll
        for (int mi = 0; mi < 2; mi++)
#pragma unroll
            for (int ni = 0; ni < 8; ni++) {
                lm[mi * 2]     = fmaxf(lm[mi * 2],     fmaxf(accs[mi][ni][0], accs[mi][ni][1]));
                lm[mi * 2 + 1] = fmaxf(lm[mi * 2 + 1], fmaxf(accs[mi][ni][2], accs[mi][ni][3]));
            }
#pragma unroll
        for (int off = 1; off <= 2; off <<= 1)
#pragma unroll
            for (int j = 0; j < 4; j++)
                lm[j] = fmaxf(lm[j], __shfl_xor_sync(0xffffffffu, lm[j], off));
        if (tg == 0) {
#pragma unroll
            for (int j = 0; j < 4; j++) {
                int rloc = wm + (j >> 1) * 16 + g + (j & 1) * 8;
                sRM[rloc][wp] = lm[j];
            }
        }
        __syncthreads();    // all S-gemm reads of sKS done before P write

        float rsum[4];
#pragma unroll
        for (int j = 0; j < 4; j++) {
            int rloc = wm + (j >> 1) * 16 + g + (j & 1) * 8;
            float tmax = fmaxf(sRM[rloc][0], sRM[rloc][1]);
            float mnew = fmaxf(m_r[j], tmax);
            float corr = __expf(m_r[j] - mnew);
            m_r[j] = mnew;
            l_r[j] *= corr;
            int mi = j >> 1, s0 = (j & 1) * 2;
            float lsum = 0.f;
#pragma unroll
            for (int ni = 0; ni < 8; ni++) {
                acc_o[mi][ni][s0]     *= corr;
                acc_o[mi][ni][s0 + 1] *= corr;
                float p0 = __expf(accs[mi][ni][s0]     - mnew);
                float p1 = __expf(accs[mi][ni][s0 + 1] - mnew);
                accs[mi][ni][s0] = p0; accs[mi][ni][s0 + 1] = p1;
                lsum += p0 + p1;
            }
            rsum[j] = lsum;
        }
#pragma unroll
        for (int off = 1; off <= 2; off <<= 1)
#pragma unroll
            for (int j = 0; j < 4; j++)
                rsum[j] += __shfl_xor_sync(0xffffffffu, rsum[j], off);
        if (tg == 0) {
#pragma unroll
            for (int j = 0; j < 4; j++) {
                int rloc = wm + (j >> 1) * 16 + g + (j & 1) * 8;
                sRS[rloc][wp] = rsum[j];
            }
        }

        // ---- write P (tf32) into the K-alias region ----
#pragma unroll
        for (int mi = 0; mi < 2; mi++)
#pragma unroll
            for (int ni = 0; ni < 8; ni++) {
                int r0 = wm + mi * 16 + g, c0 = wn + ni * 8 + tg * 2;
                sKS[r0][c0]     = f2t(accs[mi][ni][0]);
                sKS[r0][c0 + 1] = f2t(accs[mi][ni][1]);
                sKS[r0 + 8][c0]     = f2t(accs[mi][ni][2]);
                sKS[r0 + 8][c0 + 1] = f2t(accs[mi][ni][3]);
            }
        cpa_wait<0>();      // V resident
        __syncthreads();

#pragma unroll
        for (int j = 0; j < 4; j++) {
            int rloc = wm + (j >> 1) * 16 + g + (j & 1) * 8;
            l_r[j] += sRS[rloc][0] + sRS[rloc][1];
        }

        // ---- acc_o += P * V ----
#pragma unroll
        for (int ks = 0; ks < 16; ks++) {
            uint32_t af[2][4];
#pragma unroll
            for (int mi = 0; mi < 2; mi++) {
                int r = wm + mi * 16 + g, c = ks * 8 + tg;
                af[mi][0] = sKS[r][c];     af[mi][1] = sKS[r + 8][c];
                af[mi][2] = sKS[r][c + 4]; af[mi][3] = sKS[r + 8][c + 4];
            }
            uint32_t bf[8][2];
#pragma unroll
            for (int ni = 0; ni < 8; ni++) {
                int n = wn + ni * 8 + g;
                bf[ni][0] = sV[ks * 8 + tg][n];
                bf[ni][1] = sV[ks * 8 + tg + 4][n];
            }
#pragma unroll
            for (int mi = 0; mi < 2; mi++)
#pragma unroll
                for (int ni = 0; ni < 8; ni++)
                    mma8(acc_o[mi][ni], af[mi], bf[ni]);
        }
    }

    // ---- epilogue: ao = round(acc_o / l) (pre-rounded for the O-proj gemm) ----
    float* Ob = O + (size_t)(b * Sc + qt * 128) * HS + h * HDc;
#pragma unroll
    for (int mi = 0; mi < 2; mi++) {
        float inv0 = 1.f / l_r[mi * 2];
        float inv1 = 1.f / l_r[mi * 2 + 1];
#pragma unroll
        for (int ni = 0; ni < 8; ni++) {
            int r = wm + mi * 16 + g;
            int c = wn + ni * 8 + tg * 2;
            float2 v0, v1;
            v0.x = f2tf(acc_o[mi][ni][0] * inv0); v0.y = f2tf(acc_o[mi][ni][1] * inv0);
            v1.x = f2tf(acc_o[mi][ni][2] * inv1); v1.y = f2tf(acc_o[mi][ni][3] * inv1);
            *(float2*)(Ob + (size_t)r * HS + c)       = v0;
            *(float2*)(Ob + (size_t)(r + 8) * HS + c) = v1;
        }
    }
}

// ---------------------------------------------------------------------------
// Launcher
// ---------------------------------------------------------------------------
extern "C" void kernel_launch(void* const* d_in, const int* in_sizes, int n_in,
                              void* d_out, int out_size)
{
    const float* hs = (const float*)d_in[0];
    const float* wq = (const float*)d_in[1];
    const float* wk = (const float*)d_in[2];
    const float* wv = (const float*)d_in[3];
    const float* wo = (const float*)d_in[4];
    const float* cb = (const float*)d_in[5];
    const float* sb = (const float*)d_in[6];
    float* out = (float*)d_out;

    float *qp, *kp, *vp, *aop, *hsp, *wqp, *wkp, *wvp, *wop;
    cudaGetSymbolAddress((void**)&qp,  g_q);
    cudaGetSymbolAddress((void**)&kp,  g_k);
    cudaGetSymbolAddress((void**)&vp,  g_v);
    cudaGetSymbolAddress((void**)&aop, g_ao);
    cudaGetSymbolAddress((void**)&hsp, g_hs);
    cudaGetSymbolAddress((void**)&wqp, g_wq);
    cudaGetSymbolAddress((void**)&wkp, g_wk);
    cudaGetSymbolAddress((void**)&wvp, g_wv);
    cudaGetSymbolAddress((void**)&wop, g_wo);

    cudaFuncSetAttribute(gemm_tc, cudaFuncAttributeMaxDynamicSharedMemorySize, G_SMEM);
    cudaFuncSetAttribute(flash_attn, cudaFuncAttributeMaxDynamicSharedMemorySize, FL_SMEM_BYTES);

    dim3 blk(256);
    dim3 gproj(HS / 128, MR / 128);                 // (16, 32)

    const int n4_hs = MR * HS / 4;
    const int n4_w  = HS * HS / 4;

    // 5 rounding launches first (puts gemm_tc at ncu capture slot -s 5)
    round_tf32<<<(n4_hs + 255) / 256, blk>>>((const float4*)hs, (float4*)hsp, n4_hs);
    round_tf32<<<(n4_w + 255) / 256, blk>>>((const float4*)wq, (float4*)wqp, n4_w);
    round_tf32<<<(n4_w + 255) / 256, blk>>>((const float4*)wk, (float4*)wkp, n4_w);
    round_tf32<<<(n4_w + 255) / 256, blk>>>((const float4*)wv, (float4*)wvp, n4_w);
    round_tf32<<<(n4_w + 255) / 256, blk>>>((const float4*)wo, (float4*)wop, n4_w);

    gemm_tc<<<gproj, blk, G_SMEM>>>(hsp, wqp, qp, HS, HS, HS, HS, 0);
    gemm_tc<<<gproj, blk, G_SMEM>>>(hsp, wkp, kp, HS, HS, HS, HS, 0);
    gemm_tc<<<gproj, blk, G_SMEM>>>(hsp, wvp, vp, HS, HS, HS, HS, 1);  // V pre-rounded

    rope_kernel<<<dim3(MR * NHc * 64 / 256, 2), blk>>>(qp, kp, cb, sb);

    flash_attn<<<dim3(Sc / 128, BHc), blk, FL_SMEM_BYTES>>>(qp, kp, vp, aop);

    gemm_tc<<<gproj, blk, G_SMEM>>>(aop, wop, out, HS, HS, HS, HS, 0);
}

// round 6
// speedup vs baseline: 2.6338x; 1.9692x over previous
#include <cuda_runtime.h>
#include <cuda_fp16.h>
#include <cstdint>
#include <cstddef>

// Problem constants
constexpr int Bc  = 2;
constexpr int Sc  = 2048;
constexpr int HS  = 2048;
constexpr int NHc = 16;
constexpr int HDc = 128;
constexpr int MR  = Bc * Sc;    // 4096 rows of (b, s)
constexpr int BHc = Bc * NHc;   // 32 (batch*heads)
constexpr float SCALE = 0.08838834764831845f;  // 1/sqrt(128)

// Scratch (device globals — allocation-free per harness rules)
__device__ __half g_q [MR * HS];
__device__ __half g_k [MR * HS];
__device__ __half g_v [MR * HS];
__device__ __half g_ao[MR * HS];
__device__ __half g_hs[MR * HS];     // fp16 hidden states
__device__ __half g_wq[HS * HS];     // fp16 weights
__device__ __half g_wk[HS * HS];
__device__ __half g_wv[HS * HS];
__device__ __half g_wo[HS * HS];

// ---------------------------------------------------------------------------
// Helpers
// ---------------------------------------------------------------------------
__device__ __forceinline__ uint32_t smem_u32(const void* p) {
    uint32_t a;
    asm("{ .reg .u64 t; cvta.to.shared.u64 t, %1; cvt.u32.u64 %0, t; }"
        : "=r"(a) : "l"(p));
    return a;
}

__device__ __forceinline__ void cpa16(uint32_t dst, const void* src) {
    asm volatile("cp.async.cg.shared.global [%0], [%1], 16;"
                 :: "r"(dst), "l"(src) : "memory");
}
__device__ __forceinline__ void cpa_commit() {
    asm volatile("cp.async.commit_group;" ::: "memory");
}
template <int N>
__device__ __forceinline__ void cpa_wait() {
    asm volatile("cp.async.wait_group %0;" :: "n"(N) : "memory");
}

__device__ __forceinline__ void ldsm4(uint32_t* r, uint32_t a) {
    asm volatile("ldmatrix.sync.aligned.m8n8.x4.shared.b16 {%0,%1,%2,%3}, [%4];"
                 : "=r"(r[0]), "=r"(r[1]), "=r"(r[2]), "=r"(r[3]) : "r"(a));
}
__device__ __forceinline__ void ldsm4t(uint32_t* r, uint32_t a) {
    asm volatile("ldmatrix.sync.aligned.m8n8.x4.trans.shared.b16 {%0,%1,%2,%3}, [%4];"
                 : "=r"(r[0]), "=r"(r[1]), "=r"(r[2]), "=r"(r[3]) : "r"(a));
}
__device__ __forceinline__ void sts32(uint32_t addr, uint32_t v) {
    asm volatile("st.shared.b32 [%0], %1;" :: "r"(addr), "r"(v) : "memory");
}

__device__ __forceinline__ void mma16(float* c, const uint32_t* a, const uint32_t* b) {
    asm volatile(
        "mma.sync.aligned.m16n8k16.row.col.f32.f16.f16.f32 "
        "{%0,%1,%2,%3},{%4,%5,%6,%7},{%8,%9},{%0,%1,%2,%3};\n"
        : "+f"(c[0]), "+f"(c[1]), "+f"(c[2]), "+f"(c[3])
        : "r"(a[0]), "r"(a[1]), "r"(a[2]), "r"(a[3]),
          "r"(b[0]), "r"(b[1]));
}

__device__ __forceinline__ uint32_t packh2(float a, float b) {
    __half2 h = __floats2half2_rn(a, b);
    return *(uint32_t*)&h;
}

// ---------------------------------------------------------------------------
// Elementwise fp16 conversion: out = half(in)
// ---------------------------------------------------------------------------
__global__ __launch_bounds__(256) void round_fp16(
    const float4* __restrict__ in, uint2* __restrict__ out, int n4)
{
    int i = blockIdx.x * 256 + threadIdx.x;
    if (i < n4) {
        float4 v = in[i];
        uint2 o;
        o.x = packh2(v.x, v.y);
        o.y = packh2(v.z, v.w);
        out[i] = o;
    }
}

// ---------------------------------------------------------------------------
// fp16 TN GEMM: C[M,N] = A[M,K] * B[N,K]^T (row-major, halves)
// BK=64 halves, 4-stage cp.async ring, ldmatrix fragments, m16n8k16 mma.
// grid = (N/128, M/128), block = 256. smem = 4 * (16K + 16K) = 131072 B.
// Swizzle: 128B rows of 8 x 16B units; phys unit = u ^ (row & 7).
// ---------------------------------------------------------------------------
constexpr int GH_OP     = 128 * 128;      // bytes per operand tile
constexpr int GH_STAGE  = 2 * GH_OP;      // 32768
constexpr int GH_STAGES = 4;
constexpr int GH_SMEM   = GH_STAGES * GH_STAGE;   // 131072

__global__ __launch_bounds__(256) void gemm_h(
    const __half* __restrict__ A, const __half* __restrict__ B,
    void* __restrict__ Cv, int lda, int ldb, int ldc, int K, int outFloat)
{
    extern __shared__ char dsm[];
    const uint32_t sbase = smem_u32(dsm);

    const int tid  = threadIdx.x;
    const int lane = tid & 31, warp = tid >> 5;
    const int g = lane >> 2, tg = lane & 3;
    const int wm = (warp & 3) * 32, wn = (warp >> 2) * 64;

    const __half* Ab = A + (size_t)blockIdx.y * 128 * lda;
    const __half* Bb = B + (size_t)blockIdx.x * 128 * ldb;

    float acc[2][8][4];
#pragma unroll
    for (int mi = 0; mi < 2; mi++)
#pragma unroll
        for (int ni = 0; ni < 8; ni++)
#pragma unroll
            for (int j = 0; j < 4; j++) acc[mi][ni][j] = 0.f;

    auto issue = [&](int s, int k0) {
        const uint32_t stA = sbase + s * GH_STAGE;
        const uint32_t stB = stA + GH_OP;
#pragma unroll
        for (int i = 0; i < 4; i++) {
            int idx = tid + i * 256;       // 1024 units per operand
            int r = idx >> 3, u = idx & 7;
            uint32_t sw = (uint32_t)((u ^ (r & 7)) << 4);
            cpa16(stA + r * 128 + sw, Ab + (size_t)r * lda + k0 + u * 8);
            cpa16(stB + r * 128 + sw, Bb + (size_t)r * ldb + k0 + u * 8);
        }
        cpa_commit();
    };

    const int nchunk = K / 64;             // 32
    issue(0, 0); issue(1, 64); issue(2, 128);

    for (int c = 0; c < nchunk; c++) {
        cpa_wait<2>();
        __syncthreads();

        const int s = c & 3;
        const uint32_t stA = sbase + s * GH_STAGE;
        const uint32_t stB = stA + GH_OP;

#pragma unroll
        for (int ks = 0; ks < 4; ks++) {
            uint32_t af[2][4];
#pragma unroll
            for (int mi = 0; mi < 2; mi++) {
                int row = wm + 16 * mi + (lane & 15);
                int u   = 2 * ks + (lane >> 4);
                ldsm4(af[mi], stA + row * 128 + ((u ^ (row & 7)) << 4));
            }
            uint32_t bf[8][2];
#pragma unroll
            for (int nj = 0; nj < 4; nj++) {
                int row = wn + 16 * nj + (lane & 7) + ((lane & 16) >> 1);
                int u   = 2 * ks + ((lane >> 3) & 1);
                uint32_t t[4];
                ldsm4(t, stB + row * 128 + ((u ^ (row & 7)) << 4));
                bf[2 * nj][0] = t[0]; bf[2 * nj][1] = t[1];
                bf[2 * nj + 1][0] = t[2]; bf[2 * nj + 1][1] = t[3];
            }
#pragma unroll
            for (int mi = 0; mi < 2; mi++)
#pragma unroll
                for (int ni = 0; ni < 8; ni++)
                    mma16(acc[mi][ni], af[mi], bf[ni]);
        }
        __syncthreads();

        if (c + 3 < nchunk) issue((c + 3) & 3, (c + 3) * 64);
        else                cpa_commit();
    }

    const size_t rbase = (size_t)blockIdx.y * 128;
    const int cbase = blockIdx.x * 128;
    if (outFloat) {
        float* Cf = (float*)Cv;
#pragma unroll
        for (int mi = 0; mi < 2; mi++)
#pragma unroll
            for (int ni = 0; ni < 8; ni++) {
                size_t r = rbase + wm + mi * 16 + g;
                int    cc = cbase + wn + ni * 8 + tg * 2;
                float2 v0; v0.x = acc[mi][ni][0]; v0.y = acc[mi][ni][1];
                float2 v1; v1.x = acc[mi][ni][2]; v1.y = acc[mi][ni][3];
                *(float2*)(Cf + r * ldc + cc)       = v0;
                *(float2*)(Cf + (r + 8) * ldc + cc) = v1;
            }
    } else {
        __half* Ch = (__half*)Cv;
#pragma unroll
        for (int mi = 0; mi < 2; mi++)
#pragma unroll
            for (int ni = 0; ni < 8; ni++) {
                size_t r = rbase + wm + mi * 16 + g;
                int    cc = cbase + wn + ni * 8 + tg * 2;
                *(uint32_t*)(Ch + r * ldc + cc)       = packh2(acc[mi][ni][0], acc[mi][ni][1]);
                *(uint32_t*)(Ch + (r + 8) * ldc + cc) = packh2(acc[mi][ni][2], acc[mi][ni][3]);
            }
    }
}

// ---------------------------------------------------------------------------
// RoPE in place on fp16 Q and K. grid = (MR*NH*64/256, 2)
// ---------------------------------------------------------------------------
__global__ __launch_bounds__(256) void rope_h(
    __half* __restrict__ q, __half* __restrict__ k,
    const float* __restrict__ cb, const float* __restrict__ sb)
{
    int i = blockIdx.x * 256 + threadIdx.x;
    __half* arr = blockIdx.y ? k : q;
    int d   = i & 63;
    int h   = (i >> 6) & (NHc - 1);
    int row = i >> 10;
    int pos = row & (Sc - 1);
    size_t base = (size_t)row * HS + h * HDc + d;
    float x1 = __half2float(arr[base]);
    float x2 = __half2float(arr[base + 64]);
    float c  = cb[pos * HDc + d];
    float sn = sb[pos * HDc + d];
    arr[base]      = __float2half_rn(x1 * c - x2 * sn);
    arr[base + 64] = __float2half_rn(x2 * c + x1 * sn);
}

// ---------------------------------------------------------------------------
// Fused causal flash attention, fp16 operands / fp32 softmax+accum.
// grid = (16, 32) -> (qt reversed big-first, bh), block = 256.
// smem: sQ 32K | sKP 32K (K tile, later P tile) | sV 32K | sRM 1K | sRS 1K
// Rows: 256 B = 16 x 16B units; phys unit = u ^ (row & 7).
// ---------------------------------------------------------------------------
constexpr int FLH_Q  = 0;
constexpr int FLH_KP = 32768;
constexpr int FLH_V  = 65536;
constexpr int FLH_RM = 98304;
constexpr int FLH_RS = FLH_RM + 1024;
constexpr int FLH_SMEM = FLH_RS + 1024;     // 100352 B

__global__ __launch_bounds__(256) void flash_h(
    const __half* __restrict__ Q, const __half* __restrict__ K,
    const __half* __restrict__ V, __half* __restrict__ O)
{
    extern __shared__ char dsm[];
    const uint32_t sbase = smem_u32(dsm);
    const uint32_t aQ  = sbase + FLH_Q;
    const uint32_t aKP = sbase + FLH_KP;
    const uint32_t aV  = sbase + FLH_V;
    float (*sRM)[2] = (float(*)[2])(dsm + FLH_RM);
    float (*sRS)[2] = (float(*)[2])(dsm + FLH_RS);

    const int qt = (int)gridDim.x - 1 - (int)blockIdx.x;
    const int bh = blockIdx.y;
    const int b = bh >> 4, h = bh & 15;
    const int tid  = threadIdx.x;
    const int lane = tid & 31, warp = tid >> 5;
    const int g = lane >> 2, tg = lane & 3;
    const int wm = (warp & 3) * 32, wn = (warp >> 2) * 64;
    const int wp = warp >> 2;

    // Q tile: 128 rows x 128 halves = 2048 16B units, 8 per thread
    const __half* Qb = Q + (size_t)(b * Sc + qt * 128) * HS + h * HDc;
#pragma unroll
    for (int i = 0; i < 8; i++) {
        int idx = tid + i * 256;
        int r = idx >> 4, u = idx & 15;
        cpa16(aQ + r * 256 + ((u ^ (r & 7)) << 4), Qb + (size_t)r * HS + u * 8);
    }
    cpa_commit();

    float acc_o[2][8][4];
#pragma unroll
    for (int mi = 0; mi < 2; mi++)
#pragma unroll
        for (int ni = 0; ni < 8; ni++)
#pragma unroll
            for (int j = 0; j < 4; j++) acc_o[mi][ni][j] = 0.f;
    float m_r[4], l_r[4];
#pragma unroll
    for (int j = 0; j < 4; j++) { m_r[j] = -1e30f; l_r[j] = 0.f; }

    for (int kt = 0; kt <= qt; kt++) {
        const __half* Kb = K + (size_t)(b * Sc + kt * 128) * HS + h * HDc;
        const __half* Vb = V + (size_t)(b * Sc + kt * 128) * HS + h * HDc;

        __syncthreads();   // prior PV reads of sKP / sV complete
#pragma unroll
        for (int i = 0; i < 8; i++) {
            int idx = tid + i * 256;
            int r = idx >> 4, u = idx & 15;
            cpa16(aKP + r * 256 + ((u ^ (r & 7)) << 4), Kb + (size_t)r * HS + u * 8);
        }
        cpa_commit();
#pragma unroll
        for (int i = 0; i < 8; i++) {
            int idx = tid + i * 256;
            int r = idx >> 4, u = idx & 15;
            cpa16(aV + r * 256 + ((u ^ (r & 7)) << 4), Vb + (size_t)r * HS + u * 8);
        }
        cpa_commit();

        cpa_wait<1>();     // Q (first iter) + K resident; V may be in flight
        __syncthreads();

        // ---- S = Q * K^T  (8 k16-steps over HD=128) ----
        float accs[2][8][4];
#pragma unroll
        for (int mi = 0; mi < 2; mi++)
#pragma unroll
            for (int ni = 0; ni < 8; ni++)
#pragma unroll
                for (int j = 0; j < 4; j++) accs[mi][ni][j] = 0.f;

#pragma unroll
        for (int ks = 0; ks < 8; ks++) {
            uint32_t af[2][4];
#pragma unroll
            for (int mi = 0; mi < 2; mi++) {
                int row = wm + 16 * mi + (lane & 15);
                int u   = 2 * ks + (lane >> 4);
                ldsm4(af[mi], aQ + row * 256 + ((u ^ (row & 7)) << 4));
            }
            uint32_t bf[8][2];
#pragma unroll
            for (int nj = 0; nj < 4; nj++) {
                int row = wn + 16 * nj + (lane & 7) + ((lane & 16) >> 1);
                int u   = 2 * ks + ((lane >> 3) & 1);
                uint32_t t[4];
                ldsm4(t, aKP + row * 256 + ((u ^ (row & 7)) << 4));
                bf[2 * nj][0] = t[0]; bf[2 * nj][1] = t[1];
                bf[2 * nj + 1][0] = t[2]; bf[2 * nj + 1][1] = t[3];
            }
#pragma unroll
            for (int mi = 0; mi < 2; mi++)
#pragma unroll
                for (int ni = 0; ni < 8; ni++)
                    mma16(accs[mi][ni], af[mi], bf[ni]);
        }

        // ---- scale + causal mask (diagonal tile only) ----
        const bool diag = (kt == qt);
#pragma unroll
        for (int mi = 0; mi < 2; mi++)
#pragma unroll
            for (int ni = 0; ni < 8; ni++) {
                int r0 = wm + mi * 16 + g, r1 = r0 + 8;
                int c0 = wn + ni * 8 + tg * 2, c1 = c0 + 1;
                accs[mi][ni][0] *= SCALE; accs[mi][ni][1] *= SCALE;
                accs[mi][ni][2] *= SCALE; accs[mi][ni][3] *= SCALE;
                if (diag) {
                    if (c0 > r0) accs[mi][ni][0] = -1e30f;
                    if (c1 > r0) accs[mi][ni][1] = -1e30f;
                    if (c0 > r1) accs[mi][ni][2] = -1e30f;
                    if (c1 > r1) accs[mi][ni][3] = -1e30f;
                }
            }

        // ---- row max ----
        float lm[4];
#pragma unroll
        for (int j = 0; j < 4; j++) lm[j] = -1e30f;
#pragma unroll
        for (int mi = 0; mi < 2; mi++)
#pragma unroll
            for (int ni = 0; ni < 8; ni++) {
                lm[mi * 2]     = fmaxf(lm[mi * 2],     fmaxf(accs[mi][ni][0], accs[mi][ni][1]));
                lm[mi * 2 + 1] = fmaxf(lm[mi * 2 + 1], fmaxf(accs[mi][ni][2], accs[mi][ni][3]));
            }
#pragma unroll
        for (int off = 1; off <= 2; off <<= 1)
#pragma unroll
            for (int j = 0; j < 4; j++)
                lm[j] = fmaxf(lm[j], __shfl_xor_sync(0xffffffffu, lm[j], off));
        if (tg == 0) {
#pragma unroll
            for (int j = 0; j < 4; j++) {
                int rloc = wm + (j >> 1) * 16 + g + (j & 1) * 8;
                sRM[rloc][wp] = lm[j];
            }
        }
        __syncthreads();    // S reads of sKP done before P write below

        // ---- softmax update ----
        float rsum[4];
#pragma unroll
        for (int j = 0; j < 4; j++) {
            int rloc = wm + (j >> 1) * 16 + g + (j & 1) * 8;
            float tmax = fmaxf(sRM[rloc][0], sRM[rloc][1]);
            float mnew = fmaxf(m_r[j], tmax);
            float corr = __expf(m_r[j] - mnew);
            m_r[j] = mnew;
            l_r[j] *= corr;
            int mi = j >> 1, s0 = (j & 1) * 2;
            float lsum = 0.f;
#pragma unroll
            for (int ni = 0; ni < 8; ni++) {
                acc_o[mi][ni][s0]     *= corr;
                acc_o[mi][ni][s0 + 1] *= corr;
                float p0 = __expf(accs[mi][ni][s0]     - mnew);
                float p1 = __expf(accs[mi][ni][s0 + 1] - mnew);
                accs[mi][ni][s0] = p0; accs[mi][ni][s0 + 1] = p1;
                lsum += p0 + p1;
            }
            rsum[j] = lsum;
        }
#pragma unroll
        for (int off = 1; off <= 2; off <<= 1)
#pragma unroll
            for (int j = 0; j < 4; j++)
                rsum[j] += __shfl_xor_sync(0xffffffffu, rsum[j], off);
        if (tg == 0) {
#pragma unroll
            for (int j = 0; j < 4; j++) {
                int rloc = wm + (j >> 1) * 16 + g + (j & 1) * 8;
                sRS[rloc][wp] = rsum[j];
            }
        }

        // ---- write P (fp16) into the K-alias region: layout [m][k] halves ----
#pragma unroll
        for (int mi = 0; mi < 2; mi++)
#pragma unroll
            for (int ni = 0; ni < 8; ni++) {
                int r0 = wm + mi * 16 + g, r1 = r0 + 8;
                int c0 = wn + ni * 8 + tg * 2;
                int u  = c0 >> 3;
                int off = (c0 & 7) << 1;
                sts32(aKP + r0 * 256 + ((u ^ (r0 & 7)) << 4) + off,
                      packh2(accs[mi][ni][0], accs[mi][ni][1]));
                sts32(aKP + r1 * 256 + ((u ^ (r1 & 7)) << 4) + off,
                      packh2(accs[mi][ni][2], accs[mi][ni][3]));
            }
        cpa_wait<0>();      // V resident
        __syncthreads();

#pragma unroll
        for (int j = 0; j < 4; j++) {
            int rloc = wm + (j >> 1) * 16 + g + (j & 1) * 8;
            l_r[j] += sRS[rloc][0] + sRS[rloc][1];
        }

        // ---- acc_o += P(128x128) * V(128x128), V via ldmatrix.trans ----
#pragma unroll
        for (int ks = 0; ks < 8; ks++) {
            uint32_t af[2][4];
#pragma unroll
            for (int mi = 0; mi < 2; mi++) {
                int row = wm + 16 * mi + (lane & 15);
                int u   = 2 * ks + (lane >> 4);
                ldsm4(af[mi], aKP + row * 256 + ((u ^ (row & 7)) << 4));
            }
            uint32_t bf[8][2];
#pragma unroll
            for (int nj = 0; nj < 4; nj++) {
                int un   = (wn >> 3) + 2 * nj;
                int rowv = 16 * ks + (lane & 7) + (lane & 8);
                int u    = un + (lane >> 4);
                uint32_t t[4];
                ldsm4t(t, aV + rowv * 256 + ((u ^ (rowv & 7)) << 4));
                bf[2 * nj][0] = t[0]; bf[2 * nj][1] = t[1];
                bf[2 * nj + 1][0] = t[2]; bf[2 * nj + 1][1] = t[3];
            }
#pragma unroll
            for (int mi = 0; mi < 2; mi++)
#pragma unroll
                for (int ni = 0; ni < 8; ni++)
                    mma16(acc_o[mi][ni], af[mi], bf[ni]);
        }
    }

    // ---- epilogue: ao = half(acc_o / l) ----
    __half* Ob = O + (size_t)(b * Sc + qt * 128) * HS + h * HDc;
#pragma unroll
    for (int mi = 0; mi < 2; mi++) {
        float inv0 = 1.f / l_r[mi * 2];
        float inv1 = 1.f / l_r[mi * 2 + 1];
#pragma unroll
        for (int ni = 0; ni < 8; ni++) {
            int r = wm + mi * 16 + g;
            int c = wn + ni * 8 + tg * 2;
            *(uint32_t*)(Ob + (size_t)r * HS + c) =
                packh2(acc_o[mi][ni][0] * inv0, acc_o[mi][ni][1] * inv0);
            *(uint32_t*)(Ob + (size_t)(r + 8) * HS + c) =
                packh2(acc_o[mi][ni][2] * inv1, acc_o[mi][ni][3] * inv1);
        }
    }
}

// ---------------------------------------------------------------------------
// Launcher
// ---------------------------------------------------------------------------
extern "C" void kernel_launch(void* const* d_in, const int* in_sizes, int n_in,
                              void* d_out, int out_size)
{
    const float* hs = (const float*)d_in[0];
    const float* wq = (const float*)d_in[1];
    const float* wk = (const float*)d_in[2];
    const float* wv = (const float*)d_in[3];
    const float* wo = (const float*)d_in[4];
    const float* cb = (const float*)d_in[5];
    const float* sb = (const float*)d_in[6];
    float* out = (float*)d_out;

    __half *qp, *kp, *vp, *aop, *hsp, *wqp, *wkp, *wvp, *wop;
    cudaGetSymbolAddress((void**)&qp,  g_q);
    cudaGetSymbolAddress((void**)&kp,  g_k);
    cudaGetSymbolAddress((void**)&vp,  g_v);
    cudaGetSymbolAddress((void**)&aop, g_ao);
    cudaGetSymbolAddress((void**)&hsp, g_hs);
    cudaGetSymbolAddress((void**)&wqp, g_wq);
    cudaGetSymbolAddress((void**)&wkp, g_wk);
    cudaGetSymbolAddress((void**)&wvp, g_wv);
    cudaGetSymbolAddress((void**)&wop, g_wo);

    cudaFuncSetAttribute(gemm_h, cudaFuncAttributeMaxDynamicSharedMemorySize, GH_SMEM);
    cudaFuncSetAttribute(flash_h, cudaFuncAttributeMaxDynamicSharedMemorySize, FLH_SMEM);

    dim3 blk(256);
    dim3 gproj(HS / 128, MR / 128);                 // (16, 32)

    const int n4_hs = MR * HS / 4;
    const int n4_w  = HS * HS / 4;

    round_fp16<<<(n4_hs + 255) / 256, blk>>>((const float4*)hs, (uint2*)hsp, n4_hs);
    round_fp16<<<(n4_w + 255) / 256, blk>>>((const float4*)wq, (uint2*)wqp, n4_w);
    round_fp16<<<(n4_w + 255) / 256, blk>>>((const float4*)wk, (uint2*)wkp, n4_w);
    round_fp16<<<(n4_w + 255) / 256, blk>>>((const float4*)wv, (uint2*)wvp, n4_w);
    round_fp16<<<(n4_w + 255) / 256, blk>>>((const float4*)wo, (uint2*)wop, n4_w);

    gemm_h<<<gproj, blk, GH_SMEM>>>(hsp, wqp, qp, HS, HS, HS, HS, 0);
    gemm_h<<<gproj, blk, GH_SMEM>>>(hsp, wkp, kp, HS, HS, HS, HS, 0);
    gemm_h<<<gproj, blk, GH_SMEM>>>(hsp, wvp, vp, HS, HS, HS, HS, 0);

    rope_h<<<dim3(MR * NHc * 64 / 256, 2), blk>>>(qp, kp, cb, sb);

    flash_h<<<dim3(Sc / 128, BHc), blk, FLH_SMEM>>>(qp, kp, vp, aop);

    gemm_h<<<gproj, blk, GH_SMEM>>>(aop, wop, out, HS, HS, HS, HS, 1);
}

// round 7
// speedup vs baseline: 2.9936x; 1.1366x over previous
#include <cuda_runtime.h>
#include <cuda_fp16.h>
#include <cstdint>
#include <cstddef>

// Problem constants
constexpr int Bc  = 2;
constexpr int Sc  = 2048;
constexpr int HS  = 2048;
constexpr int NHc = 16;
constexpr int HDc = 128;
constexpr int MR  = Bc * Sc;    // 4096 rows of (b, s)
constexpr int BHc = Bc * NHc;   // 32 (batch*heads)
constexpr float SCALE = 0.08838834764831845f;  // 1/sqrt(128)

// Scratch (device globals — allocation-free per harness rules)
__device__ __half g_q [MR * HS];
__device__ __half g_k [MR * HS];
__device__ __half g_v [MR * HS];
__device__ __half g_ao[MR * HS];
__device__ __half g_hs[MR * HS];
__device__ __half g_wq[HS * HS];
__device__ __half g_wk[HS * HS];
__device__ __half g_wv[HS * HS];
__device__ __half g_wo[HS * HS];

// ---------------------------------------------------------------------------
// Helpers
// ---------------------------------------------------------------------------
__device__ __forceinline__ uint32_t smem_u32(const void* p) {
    uint32_t a;
    asm("{ .reg .u64 t; cvta.to.shared.u64 t, %1; cvt.u32.u64 %0, t; }"
        : "=r"(a) : "l"(p));
    return a;
}
__device__ __forceinline__ void cpa16(uint32_t dst, const void* src) {
    asm volatile("cp.async.cg.shared.global [%0], [%1], 16;"
                 :: "r"(dst), "l"(src) : "memory");
}
__device__ __forceinline__ void cpa_commit() {
    asm volatile("cp.async.commit_group;" ::: "memory");
}
template <int N>
__device__ __forceinline__ void cpa_wait() {
    asm volatile("cp.async.wait_group %0;" :: "n"(N) : "memory");
}
__device__ __forceinline__ void ldsm4(uint32_t* r, uint32_t a) {
    asm volatile("ldmatrix.sync.aligned.m8n8.x4.shared.b16 {%0,%1,%2,%3}, [%4];"
                 : "=r"(r[0]), "=r"(r[1]), "=r"(r[2]), "=r"(r[3]) : "r"(a));
}
__device__ __forceinline__ void ldsm4t(uint32_t* r, uint32_t a) {
    asm volatile("ldmatrix.sync.aligned.m8n8.x4.trans.shared.b16 {%0,%1,%2,%3}, [%4];"
                 : "=r"(r[0]), "=r"(r[1]), "=r"(r[2]), "=r"(r[3]) : "r"(a));
}
__device__ __forceinline__ void mma16(float* c, const uint32_t* a, const uint32_t* b) {
    asm volatile(
        "mma.sync.aligned.m16n8k16.row.col.f32.f16.f16.f32 "
        "{%0,%1,%2,%3},{%4,%5,%6,%7},{%8,%9},{%0,%1,%2,%3};\n"
        : "+f"(c[0]), "+f"(c[1]), "+f"(c[2]), "+f"(c[3])
        : "r"(a[0]), "r"(a[1]), "r"(a[2]), "r"(a[3]),
          "r"(b[0]), "r"(b[1]));
}
__device__ __forceinline__ uint32_t packh2(float a, float b) {
    __half2 h = __floats2half2_rn(a, b);
    return *(uint32_t*)&h;
}

// ---------------------------------------------------------------------------
// Elementwise fp16 conversion
// ---------------------------------------------------------------------------
__global__ __launch_bounds__(256) void round_fp16(
    const float4* __restrict__ in, uint2* __restrict__ out, int n4)
{
    int i = blockIdx.x * 256 + threadIdx.x;
    if (i < n4) {
        float4 v = in[i];
        uint2 o;
        o.x = packh2(v.x, v.y);
        o.y = packh2(v.z, v.w);
        out[i] = o;
    }
}

// ---------------------------------------------------------------------------
// fp16 TN GEMM body (shared by QKV-merged and O-proj kernels)
// BK=64, 4-stage cp.async ring, ldmatrix, m16n8k16.
// ---------------------------------------------------------------------------
constexpr int GH_OP     = 128 * 128;
constexpr int GH_STAGE  = 2 * GH_OP;
constexpr int GH_STAGES = 4;
constexpr int GH_SMEM   = GH_STAGES * GH_STAGE;   // 131072

template <bool OUTF>
__device__ __forceinline__ void gemm_body(
    const __half* __restrict__ A, const __half* __restrict__ B,
    void* __restrict__ Cv, int lda, int ldb, int ldc, int K, char* dsm)
{
    const uint32_t sbase = smem_u32(dsm);
    const int tid  = threadIdx.x;
    const int lane = tid & 31, warp = tid >> 5;
    const int g = lane >> 2, tg = lane & 3;
    const int wm = (warp & 3) * 32, wn = (warp >> 2) * 64;

    const __half* Ab = A + (size_t)blockIdx.y * 128 * lda;
    const __half* Bb = B + (size_t)blockIdx.x * 128 * ldb;

    float acc[2][8][4];
#pragma unroll
    for (int mi = 0; mi < 2; mi++)
#pragma unroll
        for (int ni = 0; ni < 8; ni++)
#pragma unroll
            for (int j = 0; j < 4; j++) acc[mi][ni][j] = 0.f;

    auto issue = [&](int s, int k0) {
        const uint32_t stA = sbase + s * GH_STAGE;
        const uint32_t stB = stA + GH_OP;
#pragma unroll
        for (int i = 0; i < 4; i++) {
            int idx = tid + i * 256;
            int r = idx >> 3, u = idx & 7;
            uint32_t sw = (uint32_t)((u ^ (r & 7)) << 4);
            cpa16(stA + r * 128 + sw, Ab + (size_t)r * lda + k0 + u * 8);
            cpa16(stB + r * 128 + sw, Bb + (size_t)r * ldb + k0 + u * 8);
        }
        cpa_commit();
    };

    const int nchunk = K / 64;
    issue(0, 0); issue(1, 64); issue(2, 128);

    for (int c = 0; c < nchunk; c++) {
        cpa_wait<2>();
        __syncthreads();

        const int s = c & 3;
        const uint32_t stA = sbase + s * GH_STAGE;
        const uint32_t stB = stA + GH_OP;

#pragma unroll
        for (int ks = 0; ks < 4; ks++) {
            uint32_t af[2][4];
#pragma unroll
            for (int mi = 0; mi < 2; mi++) {
                int row = wm + 16 * mi + (lane & 15);
                int u   = 2 * ks + (lane >> 4);
                ldsm4(af[mi], stA + row * 128 + ((u ^ (row & 7)) << 4));
            }
#pragma unroll
            for (int nj = 0; nj < 4; nj++) {
                int row = wn + 16 * nj + (lane & 7) + ((lane & 16) >> 1);
                int u   = 2 * ks + ((lane >> 3) & 1);
                uint32_t t[4];
                ldsm4(t, stB + row * 128 + ((u ^ (row & 7)) << 4));
#pragma unroll
                for (int mi = 0; mi < 2; mi++) {
                    mma16(acc[mi][2 * nj],     af[mi], t);
                    mma16(acc[mi][2 * nj + 1], af[mi], t + 2);
                }
            }
        }
        __syncthreads();

        if (c + 3 < nchunk) issue((c + 3) & 3, (c + 3) * 64);
        else                cpa_commit();
    }

    const size_t rbase = (size_t)blockIdx.y * 128;
    const int cbase = blockIdx.x * 128;
    if (OUTF) {
        float* Cf = (float*)Cv;
#pragma unroll
        for (int mi = 0; mi < 2; mi++)
#pragma unroll
            for (int ni = 0; ni < 8; ni++) {
                size_t r = rbase + wm + mi * 16 + g;
                int    cc = cbase + wn + ni * 8 + tg * 2;
                float2 v0; v0.x = acc[mi][ni][0]; v0.y = acc[mi][ni][1];
                float2 v1; v1.x = acc[mi][ni][2]; v1.y = acc[mi][ni][3];
                *(float2*)(Cf + r * ldc + cc)       = v0;
                *(float2*)(Cf + (r + 8) * ldc + cc) = v1;
            }
    } else {
        __half* Ch = (__half*)Cv;
#pragma unroll
        for (int mi = 0; mi < 2; mi++)
#pragma unroll
            for (int ni = 0; ni < 8; ni++) {
                size_t r = rbase + wm + mi * 16 + g;
                int    cc = cbase + wn + ni * 8 + tg * 2;
                *(uint32_t*)(Ch + r * ldc + cc)       = packh2(acc[mi][ni][0], acc[mi][ni][1]);
                *(uint32_t*)(Ch + (r + 8) * ldc + cc) = packh2(acc[mi][ni][2], acc[mi][ni][3]);
            }
    }
}

// Merged QKV projection: grid = (16, 32, 3)
__global__ __launch_bounds__(256) void gemm_qkv(
    const __half* __restrict__ A,
    const __half* __restrict__ b0, const __half* __restrict__ b1,
    const __half* __restrict__ b2,
    __half* __restrict__ c0, __half* __restrict__ c1, __half* __restrict__ c2)
{
    extern __shared__ char dsm[];
    const __half* B = (blockIdx.z == 0) ? b0 : (blockIdx.z == 1) ? b1 : b2;
    __half*       C = (blockIdx.z == 0) ? c0 : (blockIdx.z == 1) ? c1 : c2;
    gemm_body<false>(A, B, C, HS, HS, HS, HS, dsm);
}

// O projection (fp32 out)
__global__ __launch_bounds__(256) void gemm_o(
    const __half* __restrict__ A, const __half* __restrict__ B,
    float* __restrict__ C)
{
    extern __shared__ char dsm[];
    gemm_body<true>(A, B, C, HS, HS, HS, HS, dsm);
}

// ---------------------------------------------------------------------------
// RoPE in place on fp16 Q and K
// ---------------------------------------------------------------------------
__global__ __launch_bounds__(256) void rope_h(
    __half* __restrict__ q, __half* __restrict__ k,
    const float* __restrict__ cb, const float* __restrict__ sb)
{
    int i = blockIdx.x * 256 + threadIdx.x;
    __half* arr = blockIdx.y ? k : q;
    int d   = i & 63;
    int h   = (i >> 6) & (NHc - 1);
    int row = i >> 10;
    int pos = row & (Sc - 1);
    size_t base = (size_t)row * HS + h * HDc + d;
    float x1 = __half2float(arr[base]);
    float x2 = __half2float(arr[base + 64]);
    float c  = cb[pos * HDc + d];
    float sn = sb[pos * HDc + d];
    arr[base]      = __float2half_rn(x1 * c - x2 * sn);
    arr[base + 64] = __float2half_rn(x2 * c + x1 * sn);
}

// ---------------------------------------------------------------------------
// FA2-style fused causal flash attention.
// 8 warps, warp w owns rows [16w, 16w+16) x all 128 cols.
// P stays in registers (S-accum frag == A-frag layout). K/V double-buffered
// with cross-iteration prefetch; ONE __syncthreads per k-tile.
// smem: Q 32K | K[2] 64K | V[2] 64K = 160 KB.
// ---------------------------------------------------------------------------
constexpr int F_Q    = 0;
constexpr int F_K0   = 32768;
constexpr int F_V0   = 98304;
constexpr int F_SMEM = 163840;

__global__ __launch_bounds__(256) void flash_h(
    const __half* __restrict__ Q, const __half* __restrict__ K,
    const __half* __restrict__ V, __half* __restrict__ O)
{
    extern __shared__ char dsm[];
    const uint32_t sbase = smem_u32(dsm);
    const uint32_t aQ = sbase + F_Q;

    const int qt = (int)gridDim.x - 1 - (int)blockIdx.x;   // big tiles first
    const int bh = blockIdx.y;
    const int b = bh >> 4, h = bh & 15;
    const int tid  = threadIdx.x;
    const int lane = tid & 31, warp = tid >> 5;
    const int g = lane >> 2, tg = lane & 3;
    const int wr = warp * 16;                              // warp row base

    const __half* Qb = Q + (size_t)(b * Sc + qt * 128) * HS + h * HDc;
    const __half* Kb = K + (size_t)(b * Sc) * HS + h * HDc;
    const __half* Vb = V + (size_t)(b * Sc) * HS + h * HDc;

    auto load_tile = [&](uint32_t adst, const __half* src, int ktile) {
        const __half* p = src + (size_t)(ktile * 128) * HS;
#pragma unroll
        for (int i = 0; i < 8; i++) {
            int idx = tid + i * 256;
            int r = idx >> 4, u = idx & 15;
            cpa16(adst + r * 256 + ((u ^ (r & 7)) << 4), p + (size_t)r * HS + u * 8);
        }
    };

    // Prologue: Q + K0 + V0 in one group
#pragma unroll
    for (int i = 0; i < 8; i++) {
        int idx = tid + i * 256;
        int r = idx >> 4, u = idx & 15;
        cpa16(aQ + r * 256 + ((u ^ (r & 7)) << 4), Qb + (size_t)r * HS + u * 8);
    }
    load_tile(sbase + F_K0, Kb, 0);
    load_tile(sbase + F_V0, Vb, 0);
    cpa_commit();

    float acc_o[16][4];
#pragma unroll
    for (int ni = 0; ni < 16; ni++)
#pragma unroll
        for (int j = 0; j < 4; j++) acc_o[ni][j] = 0.f;
    float m0 = -1e30f, m1 = -1e30f, l0 = 0.f, l1 = 0.f;

    for (int kt = 0; kt <= qt; kt++) {
        cpa_wait<0>();
        __syncthreads();          // K[kt]/V[kt] visible; all warps done with kt-1

        if (kt < qt) {            // prefetch next tile into the other buffer
            const int nb = (kt + 1) & 1;
            load_tile(sbase + F_K0 + nb * 32768, Kb, kt + 1);
            cpa_commit();
            load_tile(sbase + F_V0 + nb * 32768, Vb, kt + 1);
            cpa_commit();
        }
        const uint32_t cK = sbase + F_K0 + (kt & 1) * 32768;
        const uint32_t cV = sbase + F_V0 + (kt & 1) * 32768;

        // ---- S = Q * K^T : warp computes 16 rows x 128 cols ----
        float accs[16][4];
#pragma unroll
        for (int ni = 0; ni < 16; ni++)
#pragma unroll
            for (int j = 0; j < 4; j++) accs[ni][j] = 0.f;

#pragma unroll
        for (int ks = 0; ks < 8; ks++) {
            uint32_t a[4];
            {
                int row = wr + (lane & 15);
                int u   = 2 * ks + (lane >> 4);
                ldsm4(a, aQ + row * 256 + ((u ^ (row & 7)) << 4));
            }
#pragma unroll
            for (int nj = 0; nj < 8; nj++) {
                int row = 16 * nj + (lane & 7) + ((lane & 16) >> 1);
                int u   = 2 * ks + ((lane >> 3) & 1);
                uint32_t t[4];
                ldsm4(t, cK + row * 256 + ((u ^ (row & 7)) << 4));
                mma16(accs[2 * nj],     a, t);
                mma16(accs[2 * nj + 1], a, t + 2);
            }
        }

        // ---- scale + causal mask ----
        const bool diag = (kt == qt);
        const int r0 = wr + g, r1 = r0 + 8;
#pragma unroll
        for (int ni = 0; ni < 16; ni++) {
            int c0 = ni * 8 + tg * 2, c1 = c0 + 1;
            accs[ni][0] *= SCALE; accs[ni][1] *= SCALE;
            accs[ni][2] *= SCALE; accs[ni][3] *= SCALE;
            if (diag) {
                if (c0 > r0) accs[ni][0] = -1e30f;
                if (c1 > r0) accs[ni][1] = -1e30f;
                if (c0 > r1) accs[ni][2] = -1e30f;
                if (c1 > r1) accs[ni][3] = -1e30f;
            }
        }

        // ---- warp-local softmax (rows fully owned; quad shuffle only) ----
        float lm0 = -1e30f, lm1 = -1e30f;
#pragma unroll
        for (int ni = 0; ni < 16; ni++) {
            lm0 = fmaxf(lm0, fmaxf(accs[ni][0], accs[ni][1]));
            lm1 = fmaxf(lm1, fmaxf(accs[ni][2], accs[ni][3]));
        }
        lm0 = fmaxf(lm0, __shfl_xor_sync(0xffffffffu, lm0, 1));
        lm0 = fmaxf(lm0, __shfl_xor_sync(0xffffffffu, lm0, 2));
        lm1 = fmaxf(lm1, __shfl_xor_sync(0xffffffffu, lm1, 1));
        lm1 = fmaxf(lm1, __shfl_xor_sync(0xffffffffu, lm1, 2));

        float mn0 = fmaxf(m0, lm0), mn1 = fmaxf(m1, lm1);
        float cr0 = __expf(m0 - mn0), cr1 = __expf(m1 - mn1);
        m0 = mn0; m1 = mn1;

        uint32_t ph[16][2];
        float ls0 = 0.f, ls1 = 0.f;
#pragma unroll
        for (int ni = 0; ni < 16; ni++) {
            float p0 = __expf(accs[ni][0] - mn0);
            float p1 = __expf(accs[ni][1] - mn0);
            float p2 = __expf(accs[ni][2] - mn1);
            float p3 = __expf(accs[ni][3] - mn1);
            ls0 += p0 + p1; ls1 += p2 + p3;
            ph[ni][0] = packh2(p0, p1);
            ph[ni][1] = packh2(p2, p3);
            acc_o[ni][0] *= cr0; acc_o[ni][1] *= cr0;
            acc_o[ni][2] *= cr1; acc_o[ni][3] *= cr1;
        }
        ls0 += __shfl_xor_sync(0xffffffffu, ls0, 1);
        ls0 += __shfl_xor_sync(0xffffffffu, ls0, 2);
        ls1 += __shfl_xor_sync(0xffffffffu, ls1, 1);
        ls1 += __shfl_xor_sync(0xffffffffu, ls1, 2);
        l0 = l0 * cr0 + ls0;
        l1 = l1 * cr1 + ls1;

        // ---- acc_o += P * V  (P from registers; V via ldmatrix.trans) ----
#pragma unroll
        for (int ks = 0; ks < 8; ks++) {
            uint32_t a[4] = { ph[2 * ks][0], ph[2 * ks][1],
                              ph[2 * ks + 1][0], ph[2 * ks + 1][1] };
#pragma unroll
            for (int nj = 0; nj < 8; nj++) {
                int rowv = 16 * ks + (lane & 7) + (lane & 8);
                int u    = 2 * nj + (lane >> 4);
                uint32_t t[4];
                ldsm4t(t, cV + rowv * 256 + ((u ^ (rowv & 7)) << 4));
                mma16(acc_o[2 * nj],     a, t);
                mma16(acc_o[2 * nj + 1], a, t + 2);
            }
        }
    }

    // ---- epilogue: ao = half(acc_o / l) ----
    __half* Ob = O + (size_t)(b * Sc + qt * 128) * HS + h * HDc;
    const float inv0 = 1.f / l0, inv1 = 1.f / l1;
    const int r0 = wr + g, r1 = r0 + 8;
#pragma unroll
    for (int ni = 0; ni < 16; ni++) {
        int c = ni * 8 + tg * 2;
        *(uint32_t*)(Ob + (size_t)r0 * HS + c) =
            packh2(acc_o[ni][0] * inv0, acc_o[ni][1] * inv0);
        *(uint32_t*)(Ob + (size_t)r1 * HS + c) =
            packh2(acc_o[ni][2] * inv1, acc_o[ni][3] * inv1);
    }
}

// ---------------------------------------------------------------------------
// Launcher
// ---------------------------------------------------------------------------
extern "C" void kernel_launch(void* const* d_in, const int* in_sizes, int n_in,
                              void* d_out, int out_size)
{
    const float* hs = (const float*)d_in[0];
    const float* wq = (const float*)d_in[1];
    const float* wk = (const float*)d_in[2];
    const float* wv = (const float*)d_in[3];
    const float* wo = (const float*)d_in[4];
    const float* cb = (const float*)d_in[5];
    const float* sb = (const float*)d_in[6];
    float* out = (float*)d_out;

    __half *qp, *kp, *vp, *aop, *hsp, *wqp, *wkp, *wvp, *wop;
    cudaGetSymbolAddress((void**)&qp,  g_q);
    cudaGetSymbolAddress((void**)&kp,  g_k);
    cudaGetSymbolAddress((void**)&vp,  g_v);
    cudaGetSymbolAddress((void**)&aop, g_ao);
    cudaGetSymbolAddress((void**)&hsp, g_hs);
    cudaGetSymbolAddress((void**)&wqp, g_wq);
    cudaGetSymbolAddress((void**)&wkp, g_wk);
    cudaGetSymbolAddress((void**)&wvp, g_wv);
    cudaGetSymbolAddress((void**)&wop, g_wo);

    cudaFuncSetAttribute(gemm_qkv, cudaFuncAttributeMaxDynamicSharedMemorySize, GH_SMEM);
    cudaFuncSetAttribute(gemm_o,   cudaFuncAttributeMaxDynamicSharedMemorySize, GH_SMEM);
    cudaFuncSetAttribute(flash_h,  cudaFuncAttributeMaxDynamicSharedMemorySize, F_SMEM);

    dim3 blk(256);

    const int n4_hs = MR * HS / 4;
    const int n4_w  = HS * HS / 4;

    round_fp16<<<(n4_hs + 255) / 256, blk>>>((const float4*)hs, (uint2*)hsp, n4_hs);
    round_fp16<<<(n4_w + 255) / 256, blk>>>((const float4*)wq, (uint2*)wqp, n4_w);
    round_fp16<<<(n4_w + 255) / 256, blk>>>((const float4*)wk, (uint2*)wkp, n4_w);
    round_fp16<<<(n4_w + 255) / 256, blk>>>((const float4*)wv, (uint2*)wvp, n4_w);
    round_fp16<<<(n4_w + 255) / 256, blk>>>((const float4*)wo, (uint2*)wop, n4_w);

    gemm_qkv<<<dim3(HS / 128, MR / 128, 3), blk, GH_SMEM>>>(
        hsp, wqp, wkp, wvp, qp, kp, vp);

    rope_h<<<dim3(MR * NHc * 64 / 256, 2), blk>>>(qp, kp, cb, sb);

    flash_h<<<dim3(Sc / 128, BHc), blk, F_SMEM>>>(qp, kp, vp, aop);

    gemm_o<<<dim3(HS / 128, MR / 128), blk, GH_SMEM>>>(aop, wop, out);
}

// round 8
// speedup vs baseline: 3.2129x; 1.0733x over previous
#include <cuda_runtime.h>
#include <cuda_fp16.h>
#include <cstdint>
#include <cstddef>

// Problem constants
constexpr int Bc  = 2;
constexpr int Sc  = 2048;
constexpr int HS  = 2048;
constexpr int NHc = 16;
constexpr int HDc = 128;
constexpr int MR  = Bc * Sc;    // 4096 rows of (b, s)
constexpr int BHc = Bc * NHc;   // 32 (batch*heads)
constexpr float SCALE = 0.08838834764831845f;  // 1/sqrt(128)

// Scratch (device globals — allocation-free per harness rules)
__device__ __half g_q [MR * HS];
__device__ __half g_k [MR * HS];
__device__ __half g_v [MR * HS];
__device__ __half g_ao[MR * HS];
__device__ __half g_hs[MR * HS];
__device__ __half g_wq[HS * HS];
__device__ __half g_wk[HS * HS];
__device__ __half g_wv[HS * HS];
__device__ __half g_wo[HS * HS];

// ---------------------------------------------------------------------------
// Helpers
// ---------------------------------------------------------------------------
__device__ __forceinline__ uint32_t smem_u32(const void* p) {
    uint32_t a;
    asm("{ .reg .u64 t; cvta.to.shared.u64 t, %1; cvt.u32.u64 %0, t; }"
        : "=r"(a) : "l"(p));
    return a;
}
__device__ __forceinline__ void cpa16(uint32_t dst, const void* src) {
    asm volatile("cp.async.cg.shared.global [%0], [%1], 16;"
                 :: "r"(dst), "l"(src) : "memory");
}
__device__ __forceinline__ void cpa_commit() {
    asm volatile("cp.async.commit_group;" ::: "memory");
}
template <int N>
__device__ __forceinline__ void cpa_wait() {
    asm volatile("cp.async.wait_group %0;" :: "n"(N) : "memory");
}
__device__ __forceinline__ void ldsm4(uint32_t* r, uint32_t a) {
    asm volatile("ldmatrix.sync.aligned.m8n8.x4.shared.b16 {%0,%1,%2,%3}, [%4];"
                 : "=r"(r[0]), "=r"(r[1]), "=r"(r[2]), "=r"(r[3]) : "r"(a));
}
__device__ __forceinline__ void ldsm4t(uint32_t* r, uint32_t a) {
    asm volatile("ldmatrix.sync.aligned.m8n8.x4.trans.shared.b16 {%0,%1,%2,%3}, [%4];"
                 : "=r"(r[0]), "=r"(r[1]), "=r"(r[2]), "=r"(r[3]) : "r"(a));
}
__device__ __forceinline__ void mma16(float* c, const uint32_t* a, const uint32_t* b) {
    asm volatile(
        "mma.sync.aligned.m16n8k16.row.col.f32.f16.f16.f32 "
        "{%0,%1,%2,%3},{%4,%5,%6,%7},{%8,%9},{%0,%1,%2,%3};\n"
        : "+f"(c[0]), "+f"(c[1]), "+f"(c[2]), "+f"(c[3])
        : "r"(a[0]), "r"(a[1]), "r"(a[2]), "r"(a[3]),
          "r"(b[0]), "r"(b[1]));
}
__device__ __forceinline__ uint32_t packh2(float a, float b) {
    __half2 h = __floats2half2_rn(a, b);
    return *(uint32_t*)&h;
}

// ---------------------------------------------------------------------------
// Elementwise fp16 conversion (hs)
// ---------------------------------------------------------------------------
__global__ __launch_bounds__(256) void round_fp16(
    const float4* __restrict__ in, uint2* __restrict__ out, int n4)
{
    int i = blockIdx.x * 256 + threadIdx.x;
    if (i < n4) {
        float4 v = in[i];
        uint2 o;
        o.x = packh2(v.x, v.y);
        o.y = packh2(v.z, v.w);
        out[i] = o;
    }
}

// Merged 4-weight conversion: grid = (n4/256, 4)
__global__ __launch_bounds__(256) void round_fp16w(
    const float4* __restrict__ w0, const float4* __restrict__ w1,
    const float4* __restrict__ w2, const float4* __restrict__ w3,
    uint2* __restrict__ o0, uint2* __restrict__ o1,
    uint2* __restrict__ o2, uint2* __restrict__ o3, int n4)
{
    const float4* in  = (blockIdx.y == 0) ? w0 : (blockIdx.y == 1) ? w1
                      : (blockIdx.y == 2) ? w2 : w3;
    uint2*        out = (blockIdx.y == 0) ? o0 : (blockIdx.y == 1) ? o1
                      : (blockIdx.y == 2) ? o2 : o3;
    int i = blockIdx.x * 256 + threadIdx.x;
    if (i < n4) {
        float4 v = in[i];
        uint2 o;
        o.x = packh2(v.x, v.y);
        o.y = packh2(v.z, v.w);
        out[i] = o;
    }
}

// ---------------------------------------------------------------------------
// fp16 TN GEMM: C[M,N] = A[M,K] * B[N,K]^T
// Block tile 128(M) x 256(N), warp tile 64x64 (warps 2x4), BK=64 halves.
// 4-stage cp.async ring (48KB/stage = 192KB), ONE sync per chunk.
// ---------------------------------------------------------------------------
constexpr int GB_N      = 256;
constexpr int GH_A      = 128 * 128;          // A bytes / stage (128 rows x 128B)
constexpr int GH_B      = 256 * 128;          // B bytes / stage
constexpr int GH_STAGE  = GH_A + GH_B;        // 49152
constexpr int GH_SMEM   = 4 * GH_STAGE;       // 196608

template <bool OUTF>
__device__ __forceinline__ void gemm_body(
    const __half* __restrict__ A, const __half* __restrict__ B,
    void* __restrict__ Cv, int lda, int ldb, int ldc, int K, char* dsm)
{
    const uint32_t sbase = smem_u32(dsm);
    const int tid  = threadIdx.x;
    const int lane = tid & 31, warp = tid >> 5;
    const int g = lane >> 2, tg = lane & 3;
    const int wm = (warp >> 2) * 64;          // 0 or 64
    const int wn = (warp & 3) * 64;           // 0,64,128,192

    const __half* Ab = A + (size_t)blockIdx.y * 128 * lda;
    const __half* Bb = B + (size_t)blockIdx.x * GB_N * ldb;

    float acc[4][8][4];
#pragma unroll
    for (int mi = 0; mi < 4; mi++)
#pragma unroll
        for (int ni = 0; ni < 8; ni++)
#pragma unroll
            for (int j = 0; j < 4; j++) acc[mi][ni][j] = 0.f;

    auto issue = [&](int s, int k0) {
        const uint32_t stA = sbase + s * GH_STAGE;
        const uint32_t stB = stA + GH_A;
#pragma unroll
        for (int i = 0; i < 4; i++) {          // A: 1024 16B units
            int idx = tid + i * 256;
            int r = idx >> 3, u = idx & 7;
            cpa16(stA + r * 128 + ((u ^ (r & 7)) << 4),
                  Ab + (size_t)r * lda + k0 + u * 8);
        }
#pragma unroll
        for (int i = 0; i < 8; i++) {          // B: 2048 16B units
            int idx = tid + i * 256;
            int r = idx >> 3, u = idx & 7;
            cpa16(stB + r * 128 + ((u ^ (r & 7)) << 4),
                  Bb + (size_t)r * ldb + k0 + u * 8);
        }
        cpa_commit();
    };

    const int nchunk = K / 64;                 // 32
    issue(0, 0); issue(1, 64); issue(2, 128);

    for (int c = 0; c < nchunk; c++) {
        cpa_wait<2>();
        __syncthreads();   // stage c ready; all warps done computing stage c-1

        // Issue next stage now: buffer (c+3)&3 was last READ at iter c-1,
        // and the barrier above orders those reads before these writes.
        if (c + 3 < nchunk) issue((c + 3) & 3, (c + 3) * 64);
        else                cpa_commit();

        const int s = c & 3;
        const uint32_t stA = sbase + s * GH_STAGE;
        const uint32_t stB = stA + GH_A;

#pragma unroll
        for (int ks = 0; ks < 4; ks++) {
            uint32_t af[4][4];
#pragma unroll
            for (int mi = 0; mi < 4; mi++) {
                int row = wm + 16 * mi + (lane & 15);
                int u   = 2 * ks + (lane >> 4);
                ldsm4(af[mi], stA + row * 128 + ((u ^ (row & 7)) << 4));
            }
#pragma unroll
            for (int nj = 0; nj < 4; nj++) {
                int row = wn + 16 * nj + (lane & 7) + ((lane & 16) >> 1);
                int u   = 2 * ks + ((lane >> 3) & 1);
                uint32_t t[4];
                ldsm4(t, stB + row * 128 + ((u ^ (row & 7)) << 4));
#pragma unroll
                for (int mi = 0; mi < 4; mi++) {
                    mma16(acc[mi][2 * nj],     af[mi], t);
                    mma16(acc[mi][2 * nj + 1], af[mi], t + 2);
                }
            }
        }
    }

    const size_t rbase = (size_t)blockIdx.y * 128;
    const int cbase = blockIdx.x * GB_N;
    if (OUTF) {
        float* Cf = (float*)Cv;
#pragma unroll
        for (int mi = 0; mi < 4; mi++)
#pragma unroll
            for (int ni = 0; ni < 8; ni++) {
                size_t r = rbase + wm + mi * 16 + g;
                int    cc = cbase + wn + ni * 8 + tg * 2;
                float2 v0; v0.x = acc[mi][ni][0]; v0.y = acc[mi][ni][1];
                float2 v1; v1.x = acc[mi][ni][2]; v1.y = acc[mi][ni][3];
                *(float2*)(Cf + r * ldc + cc)       = v0;
                *(float2*)(Cf + (r + 8) * ldc + cc) = v1;
            }
    } else {
        __half* Ch = (__half*)Cv;
#pragma unroll
        for (int mi = 0; mi < 4; mi++)
#pragma unroll
            for (int ni = 0; ni < 8; ni++) {
                size_t r = rbase + wm + mi * 16 + g;
                int    cc = cbase + wn + ni * 8 + tg * 2;
                *(uint32_t*)(Ch + r * ldc + cc)       = packh2(acc[mi][ni][0], acc[mi][ni][1]);
                *(uint32_t*)(Ch + (r + 8) * ldc + cc) = packh2(acc[mi][ni][2], acc[mi][ni][3]);
            }
    }
}

// Merged QKV projection: grid = (HS/256, MR/128, 3)
__global__ __launch_bounds__(256) void gemm_qkv(
    const __half* __restrict__ A,
    const __half* __restrict__ b0, const __half* __restrict__ b1,
    const __half* __restrict__ b2,
    __half* __restrict__ c0, __half* __restrict__ c1, __half* __restrict__ c2)
{
    extern __shared__ char dsm[];
    const __half* B = (blockIdx.z == 0) ? b0 : (blockIdx.z == 1) ? b1 : b2;
    __half*       C = (blockIdx.z == 0) ? c0 : (blockIdx.z == 1) ? c1 : c2;
    gemm_body<false>(A, B, C, HS, HS, HS, HS, dsm);
}

// O projection (fp32 out): grid = (HS/256, MR/128)
__global__ __launch_bounds__(256) void gemm_o(
    const __half* __restrict__ A, const __half* __restrict__ B,
    float* __restrict__ C)
{
    extern __shared__ char dsm[];
    gemm_body<true>(A, B, C, HS, HS, HS, HS, dsm);
}

// ---------------------------------------------------------------------------
// RoPE in place on fp16 Q and K
// ---------------------------------------------------------------------------
__global__ __launch_bounds__(256) void rope_h(
    __half* __restrict__ q, __half* __restrict__ k,
    const float* __restrict__ cb, const float* __restrict__ sb)
{
    int i = blockIdx.x * 256 + threadIdx.x;
    __half* arr = blockIdx.y ? k : q;
    int d   = i & 63;
    int h   = (i >> 6) & (NHc - 1);
    int row = i >> 10;
    int pos = row & (Sc - 1);
    size_t base = (size_t)row * HS + h * HDc + d;
    float x1 = __half2float(arr[base]);
    float x2 = __half2float(arr[base + 64]);
    float c  = cb[pos * HDc + d];
    float sn = sb[pos * HDc + d];
    arr[base]      = __float2half_rn(x1 * c - x2 * sn);
    arr[base + 64] = __float2half_rn(x2 * c + x1 * sn);
}

// ---------------------------------------------------------------------------
// FA2-style fused causal flash attention (unchanged from round 7).
// ---------------------------------------------------------------------------
constexpr int F_Q    = 0;
constexpr int F_K0   = 32768;
constexpr int F_V0   = 98304;
constexpr int F_SMEM = 163840;

__global__ __launch_bounds__(256) void flash_h(
    const __half* __restrict__ Q, const __half* __restrict__ K,
    const __half* __restrict__ V, __half* __restrict__ O)
{
    extern __shared__ char dsm[];
    const uint32_t sbase = smem_u32(dsm);
    const uint32_t aQ = sbase + F_Q;

    const int qt = (int)gridDim.x - 1 - (int)blockIdx.x;
    const int bh = blockIdx.y;
    const int b = bh >> 4, h = bh & 15;
    const int tid  = threadIdx.x;
    const int lane = tid & 31, warp = tid >> 5;
    const int g = lane >> 2, tg = lane & 3;
    const int wr = warp * 16;

    const __half* Qb = Q + (size_t)(b * Sc + qt * 128) * HS + h * HDc;
    const __half* Kb = K + (size_t)(b * Sc) * HS + h * HDc;
    const __half* Vb = V + (size_t)(b * Sc) * HS + h * HDc;

    auto load_tile = [&](uint32_t adst, const __half* src, int ktile) {
        const __half* p = src + (size_t)(ktile * 128) * HS;
#pragma unroll
        for (int i = 0; i < 8; i++) {
            int idx = tid + i * 256;
            int r = idx >> 4, u = idx & 15;
            cpa16(adst + r * 256 + ((u ^ (r & 7)) << 4), p + (size_t)r * HS + u * 8);
        }
    };

#pragma unroll
    for (int i = 0; i < 8; i++) {
        int idx = tid + i * 256;
        int r = idx >> 4, u = idx & 15;
        cpa16(aQ + r * 256 + ((u ^ (r & 7)) << 4), Qb + (size_t)r * HS + u * 8);
    }
    load_tile(sbase + F_K0, Kb, 0);
    load_tile(sbase + F_V0, Vb, 0);
    cpa_commit();

    float acc_o[16][4];
#pragma unroll
    for (int ni = 0; ni < 16; ni++)
#pragma unroll
        for (int j = 0; j < 4; j++) acc_o[ni][j] = 0.f;
    float m0 = -1e30f, m1 = -1e30f, l0 = 0.f, l1 = 0.f;

    for (int kt = 0; kt <= qt; kt++) {
        cpa_wait<0>();
        __syncthreads();

        if (kt < qt) {
            const int nb = (kt + 1) & 1;
            load_tile(sbase + F_K0 + nb * 32768, Kb, kt + 1);
            cpa_commit();
            load_tile(sbase + F_V0 + nb * 32768, Vb, kt + 1);
            cpa_commit();
        }
        const uint32_t cK = sbase + F_K0 + (kt & 1) * 32768;
        const uint32_t cV = sbase + F_V0 + (kt & 1) * 32768;

        float accs[16][4];
#pragma unroll
        for (int ni = 0; ni < 16; ni++)
#pragma unroll
            for (int j = 0; j < 4; j++) accs[ni][j] = 0.f;

#pragma unroll
        for (int ks = 0; ks < 8; ks++) {
            uint32_t a[4];
            {
                int row = wr + (lane & 15);
                int u   = 2 * ks + (lane >> 4);
                ldsm4(a, aQ + row * 256 + ((u ^ (row & 7)) << 4));
            }
#pragma unroll
            for (int nj = 0; nj < 8; nj++) {
                int row = 16 * nj + (lane & 7) + ((lane & 16) >> 1);
                int u   = 2 * ks + ((lane >> 3) & 1);
                uint32_t t[4];
                ldsm4(t, cK + row * 256 + ((u ^ (row & 7)) << 4));
                mma16(accs[2 * nj],     a, t);
                mma16(accs[2 * nj + 1], a, t + 2);
            }
        }

        const bool diag = (kt == qt);
        const int r0 = wr + g, r1 = r0 + 8;
#pragma unroll
        for (int ni = 0; ni < 16; ni++) {
            int c0 = ni * 8 + tg * 2, c1 = c0 + 1;
            accs[ni][0] *= SCALE; accs[ni][1] *= SCALE;
            accs[ni][2] *= SCALE; accs[ni][3] *= SCALE;
            if (diag) {
                if (c0 > r0) accs[ni][0] = -1e30f;
                if (c1 > r0) accs[ni][1] = -1e30f;
                if (c0 > r1) accs[ni][2] = -1e30f;
                if (c1 > r1) accs[ni][3] = -1e30f;
            }
        }

        float lm0 = -1e30f, lm1 = -1e30f;
#pragma unroll
        for (int ni = 0; ni < 16; ni++) {
            lm0 = fmaxf(lm0, fmaxf(accs[ni][0], accs[ni][1]));
            lm1 = fmaxf(lm1, fmaxf(accs[ni][2], accs[ni][3]));
        }
        lm0 = fmaxf(lm0, __shfl_xor_sync(0xffffffffu, lm0, 1));
        lm0 = fmaxf(lm0, __shfl_xor_sync(0xffffffffu, lm0, 2));
        lm1 = fmaxf(lm1, __shfl_xor_sync(0xffffffffu, lm1, 1));
        lm1 = fmaxf(lm1, __shfl_xor_sync(0xffffffffu, lm1, 2));

        float mn0 = fmaxf(m0, lm0), mn1 = fmaxf(m1, lm1);
        float cr0 = __expf(m0 - mn0), cr1 = __expf(m1 - mn1);
        m0 = mn0; m1 = mn1;

        uint32_t ph[16][2];
        float ls0 = 0.f, ls1 = 0.f;
#pragma unroll
        for (int ni = 0; ni < 16; ni++) {
            float p0 = __expf(accs[ni][0] - mn0);
            float p1 = __expf(accs[ni][1] - mn0);
            float p2 = __expf(accs[ni][2] - mn1);
            float p3 = __expf(accs[ni][3] - mn1);
            ls0 += p0 + p1; ls1 += p2 + p3;
            ph[ni][0] = packh2(p0, p1);
            ph[ni][1] = packh2(p2, p3);
            acc_o[ni][0] *= cr0; acc_o[ni][1] *= cr0;
            acc_o[ni][2] *= cr1; acc_o[ni][3] *= cr1;
        }
        ls0 += __shfl_xor_sync(0xffffffffu, ls0, 1);
        ls0 += __shfl_xor_sync(0xffffffffu, ls0, 2);
        ls1 += __shfl_xor_sync(0xffffffffu, ls1, 1);
        ls1 += __shfl_xor_sync(0xffffffffu, ls1, 2);
        l0 = l0 * cr0 + ls0;
        l1 = l1 * cr1 + ls1;

#pragma unroll
        for (int ks = 0; ks < 8; ks++) {
            uint32_t a[4] = { ph[2 * ks][0], ph[2 * ks][1],
                              ph[2 * ks + 1][0], ph[2 * ks + 1][1] };
#pragma unroll
            for (int nj = 0; nj < 8; nj++) {
                int rowv = 16 * ks + (lane & 7) + (lane & 8);
                int u    = 2 * nj + (lane >> 4);
                uint32_t t[4];
                ldsm4t(t, cV + rowv * 256 + ((u ^ (rowv & 7)) << 4));
                mma16(acc_o[2 * nj],     a, t);
                mma16(acc_o[2 * nj + 1], a, t + 2);
            }
        }
    }

    __half* Ob = O + (size_t)(b * Sc + qt * 128) * HS + h * HDc;
    const float inv0 = 1.f / l0, inv1 = 1.f / l1;
    const int r0 = wr + g, r1 = r0 + 8;
#pragma unroll
    for (int ni = 0; ni < 16; ni++) {
        int c = ni * 8 + tg * 2;
        *(uint32_t*)(Ob + (size_t)r0 * HS + c) =
            packh2(acc_o[ni][0] * inv0, acc_o[ni][1] * inv0);
        *(uint32_t*)(Ob + (size_t)r1 * HS + c) =
            packh2(acc_o[ni][2] * inv1, acc_o[ni][3] * inv1);
    }
}

// ---------------------------------------------------------------------------
// Launcher
// ---------------------------------------------------------------------------
extern "C" void kernel_launch(void* const* d_in, const int* in_sizes, int n_in,
                              void* d_out, int out_size)
{
    const float* hs = (const float*)d_in[0];
    const float* wq = (const float*)d_in[1];
    const float* wk = (const float*)d_in[2];
    const float* wv = (const float*)d_in[3];
    const float* wo = (const float*)d_in[4];
    const float* cb = (const float*)d_in[5];
    const float* sb = (const float*)d_in[6];
    float* out = (float*)d_out;

    __half *qp, *kp, *vp, *aop, *hsp, *wqp, *wkp, *wvp, *wop;
    cudaGetSymbolAddress((void**)&qp,  g_q);
    cudaGetSymbolAddress((void**)&kp,  g_k);
    cudaGetSymbolAddress((void**)&vp,  g_v);
    cudaGetSymbolAddress((void**)&aop, g_ao);
    cudaGetSymbolAddress((void**)&hsp, g_hs);
    cudaGetSymbolAddress((void**)&wqp, g_wq);
    cudaGetSymbolAddress((void**)&wkp, g_wk);
    cudaGetSymbolAddress((void**)&wvp, g_wv);
    cudaGetSymbolAddress((void**)&wop, g_wo);

    cudaFuncSetAttribute(gemm_qkv, cudaFuncAttributeMaxDynamicSharedMemorySize, GH_SMEM);
    cudaFuncSetAttribute(gemm_o,   cudaFuncAttributeMaxDynamicSharedMemorySize, GH_SMEM);
    cudaFuncSetAttribute(flash_h,  cudaFuncAttributeMaxDynamicSharedMemorySize, F_SMEM);

    dim3 blk(256);

    const int n4_hs = MR * HS / 4;
    const int n4_w  = HS * HS / 4;

    round_fp16<<<(n4_hs + 255) / 256, blk>>>((const float4*)hs, (uint2*)hsp, n4_hs);
    round_fp16w<<<dim3((n4_w + 255) / 256, 4), blk>>>(
        (const float4*)wq, (const float4*)wk, (const float4*)wv, (const float4*)wo,
        (uint2*)wqp, (uint2*)wkp, (uint2*)wvp, (uint2*)wop, n4_w);

    gemm_qkv<<<dim3(HS / GB_N, MR / 128, 3), blk, GH_SMEM>>>(
        hsp, wqp, wkp, wvp, qp, kp, vp);

    rope_h<<<dim3(MR * NHc * 64 / 256, 2), blk>>>(qp, kp, cb, sb);

    flash_h<<<dim3(Sc / 128, BHc), blk, F_SMEM>>>(qp, kp, vp, aop);

    gemm_o<<<dim3(HS / GB_N, MR / 128), blk, GH_SMEM>>>(aop, wop, out);
}

// round 9
// speedup vs baseline: 3.2908x; 1.0243x over previous
#include <cuda_runtime.h>
#include <cuda_fp16.h>
#include <cstdint>
#include <cstddef>

// Problem constants
constexpr int Bc  = 2;
constexpr int Sc  = 2048;
constexpr int HS  = 2048;
constexpr int NHc = 16;
constexpr int HDc = 128;
constexpr int MR  = Bc * Sc;    // 4096 rows of (b, s)
constexpr int BHc = Bc * NHc;   // 32 (batch*heads)
constexpr float SCALE = 0.08838834764831845f;  // 1/sqrt(128)

// Scratch (device globals — allocation-free per harness rules)
__device__ __half g_q [MR * HS];
__device__ __half g_k [MR * HS];
__device__ __half g_v [MR * HS];
__device__ __half g_ao[MR * HS];
__device__ __half g_hs[MR * HS];
__device__ __half g_wq[HS * HS];
__device__ __half g_wk[HS * HS];
__device__ __half g_wv[HS * HS];
__device__ __half g_wo[HS * HS];

// ---------------------------------------------------------------------------
// Helpers
// ---------------------------------------------------------------------------
__device__ __forceinline__ uint32_t smem_u32(const void* p) {
    uint32_t a;
    asm("{ .reg .u64 t; cvta.to.shared.u64 t, %1; cvt.u32.u64 %0, t; }"
        : "=r"(a) : "l"(p));
    return a;
}
__device__ __forceinline__ void cpa16(uint32_t dst, const void* src) {
    asm volatile("cp.async.cg.shared.global [%0], [%1], 16;"
                 :: "r"(dst), "l"(src) : "memory");
}
__device__ __forceinline__ void cpa_commit() {
    asm volatile("cp.async.commit_group;" ::: "memory");
}
template <int N>
__device__ __forceinline__ void cpa_wait() {
    asm volatile("cp.async.wait_group %0;" :: "n"(N) : "memory");
}
__device__ __forceinline__ void ldsm4(uint32_t* r, uint32_t a) {
    asm volatile("ldmatrix.sync.aligned.m8n8.x4.shared.b16 {%0,%1,%2,%3}, [%4];"
                 : "=r"(r[0]), "=r"(r[1]), "=r"(r[2]), "=r"(r[3]) : "r"(a));
}
__device__ __forceinline__ void ldsm4t(uint32_t* r, uint32_t a) {
    asm volatile("ldmatrix.sync.aligned.m8n8.x4.trans.shared.b16 {%0,%1,%2,%3}, [%4];"
                 : "=r"(r[0]), "=r"(r[1]), "=r"(r[2]), "=r"(r[3]) : "r"(a));
}
__device__ __forceinline__ void mma16(float* c, const uint32_t* a, const uint32_t* b) {
    asm volatile(
        "mma.sync.aligned.m16n8k16.row.col.f32.f16.f16.f32 "
        "{%0,%1,%2,%3},{%4,%5,%6,%7},{%8,%9},{%0,%1,%2,%3};\n"
        : "+f"(c[0]), "+f"(c[1]), "+f"(c[2]), "+f"(c[3])
        : "r"(a[0]), "r"(a[1]), "r"(a[2]), "r"(a[3]),
          "r"(b[0]), "r"(b[1]));
}
__device__ __forceinline__ uint32_t packh2(float a, float b) {
    __half2 h = __floats2half2_rn(a, b);
    return *(uint32_t*)&h;
}

// ---------------------------------------------------------------------------
// Merged fp16 conversion: grid = (8192, 5). y=0: hs (n4=2M); y=1..4: weights.
// ---------------------------------------------------------------------------
__global__ __launch_bounds__(256) void round_all(
    const float4* __restrict__ hs, const float4* __restrict__ w0,
    const float4* __restrict__ w1, const float4* __restrict__ w2,
    const float4* __restrict__ w3,
    uint2* __restrict__ ohs, uint2* __restrict__ o0, uint2* __restrict__ o1,
    uint2* __restrict__ o2, uint2* __restrict__ o3)
{
    const int y = blockIdx.y;
    const float4* in  = (y == 0) ? hs : (y == 1) ? w0 : (y == 2) ? w1
                      : (y == 3) ? w2 : w3;
    uint2*        out = (y == 0) ? ohs : (y == 1) ? o0 : (y == 2) ? o1
                      : (y == 3) ? o2 : o3;
    const int n4 = (y == 0) ? (MR * HS / 4) : (HS * HS / 4);
    int i = blockIdx.x * 256 + threadIdx.x;
    if (i < n4) {
        float4 v = in[i];
        uint2 o;
        o.x = packh2(v.x, v.y);
        o.y = packh2(v.z, v.w);
        out[i] = o;
    }
}

// ---------------------------------------------------------------------------
// fp16 TN GEMM: C[M,N] = A[M,K] * B[N,K]^T
// Block tile 128(M) x 256(N), warp tile 64x64 (warps 2x4), BK=64 halves.
// 4-stage cp.async ring (48KB/stage = 192KB), ONE sync per chunk.
// Optional fused RoPE epilogue (doRope): stage tile in smem, apply rotary.
// ---------------------------------------------------------------------------
constexpr int GB_N      = 256;
constexpr int GH_A      = 128 * 128;
constexpr int GH_B      = 256 * 128;
constexpr int GH_STAGE  = GH_A + GH_B;        // 49152
constexpr int GH_SMEM   = 4 * GH_STAGE;       // 196608
constexpr int RT_STRIDE = 132;                // uint32 (h2) per staged row

template <bool OUTF>
__device__ __forceinline__ void gemm_body(
    const __half* __restrict__ A, const __half* __restrict__ B,
    void* __restrict__ Cv, int lda, int ldb, int ldc, int K, char* dsm,
    const float* __restrict__ cb, const float* __restrict__ sb, bool doRope)
{
    const uint32_t sbase = smem_u32(dsm);
    const int tid  = threadIdx.x;
    const int lane = tid & 31, warp = tid >> 5;
    const int g = lane >> 2, tg = lane & 3;
    const int wm = (warp >> 2) * 64;
    const int wn = (warp & 3) * 64;

    const __half* Ab = A + (size_t)blockIdx.y * 128 * lda;
    const __half* Bb = B + (size_t)blockIdx.x * GB_N * ldb;

    float acc[4][8][4];
#pragma unroll
    for (int mi = 0; mi < 4; mi++)
#pragma unroll
        for (int ni = 0; ni < 8; ni++)
#pragma unroll
            for (int j = 0; j < 4; j++) acc[mi][ni][j] = 0.f;

    auto issue = [&](int s, int k0) {
        const uint32_t stA = sbase + s * GH_STAGE;
        const uint32_t stB = stA + GH_A;
#pragma unroll
        for (int i = 0; i < 4; i++) {
            int idx = tid + i * 256;
            int r = idx >> 3, u = idx & 7;
            cpa16(stA + r * 128 + ((u ^ (r & 7)) << 4),
                  Ab + (size_t)r * lda + k0 + u * 8);
        }
#pragma unroll
        for (int i = 0; i < 8; i++) {
            int idx = tid + i * 256;
            int r = idx >> 3, u = idx & 7;
            cpa16(stB + r * 128 + ((u ^ (r & 7)) << 4),
                  Bb + (size_t)r * ldb + k0 + u * 8);
        }
        cpa_commit();
    };

    const int nchunk = K / 64;
    issue(0, 0); issue(1, 64); issue(2, 128);

    for (int c = 0; c < nchunk; c++) {
        cpa_wait<2>();
        __syncthreads();

        if (c + 3 < nchunk) issue((c + 3) & 3, (c + 3) * 64);
        else                cpa_commit();

        const int s = c & 3;
        const uint32_t stA = sbase + s * GH_STAGE;
        const uint32_t stB = stA + GH_A;

#pragma unroll
        for (int ks = 0; ks < 4; ks++) {
            uint32_t af[4][4];
#pragma unroll
            for (int mi = 0; mi < 4; mi++) {
                int row = wm + 16 * mi + (lane & 15);
                int u   = 2 * ks + (lane >> 4);
                ldsm4(af[mi], stA + row * 128 + ((u ^ (row & 7)) << 4));
            }
#pragma unroll
            for (int nj = 0; nj < 4; nj++) {
                int row = wn + 16 * nj + (lane & 7) + ((lane & 16) >> 1);
                int u   = 2 * ks + ((lane >> 3) & 1);
                uint32_t t[4];
                ldsm4(t, stB + row * 128 + ((u ^ (row & 7)) << 4));
#pragma unroll
                for (int mi = 0; mi < 4; mi++) {
                    mma16(acc[mi][2 * nj],     af[mi], t);
                    mma16(acc[mi][2 * nj + 1], af[mi], t + 2);
                }
            }
        }
    }

    const size_t rbase = (size_t)blockIdx.y * 128;
    const int cbase = blockIdx.x * GB_N;

    if (OUTF) {
        float* Cf = (float*)Cv;
#pragma unroll
        for (int mi = 0; mi < 4; mi++)
#pragma unroll
            for (int ni = 0; ni < 8; ni++) {
                size_t r = rbase + wm + mi * 16 + g;
                int    cc = cbase + wn + ni * 8 + tg * 2;
                float2 v0; v0.x = acc[mi][ni][0]; v0.y = acc[mi][ni][1];
                float2 v1; v1.x = acc[mi][ni][2]; v1.y = acc[mi][ni][3];
                *(float2*)(Cf + r * ldc + cc)       = v0;
                *(float2*)(Cf + (r + 8) * ldc + cc) = v1;
            }
        return;
    }

    __half* Ch = (__half*)Cv;
    if (!doRope) {
#pragma unroll
        for (int mi = 0; mi < 4; mi++)
#pragma unroll
            for (int ni = 0; ni < 8; ni++) {
                size_t r = rbase + wm + mi * 16 + g;
                int    cc = cbase + wn + ni * 8 + tg * 2;
                *(uint32_t*)(Ch + r * ldc + cc)       = packh2(acc[mi][ni][0], acc[mi][ni][1]);
                *(uint32_t*)(Ch + (r + 8) * ldc + cc) = packh2(acc[mi][ni][2], acc[mi][ni][3]);
            }
        return;
    }

    // ---- fused RoPE epilogue ----
    // Stage tile (fp16) into ring smem stages 0/1 region: rows 128 x 132 h2.
    // Safe without a pre-barrier: staging area covers stages 0/1, whose last
    // reads (iters 28/29) completed before the final loop barriers.
    uint32_t* sT = (uint32_t*)dsm;
#pragma unroll
    for (int mi = 0; mi < 4; mi++)
#pragma unroll
        for (int ni = 0; ni < 8; ni++) {
            int r  = wm + mi * 16 + g;
            int c2 = (wn + ni * 8 + tg * 2) >> 1;
            sT[r * RT_STRIDE + c2]       = packh2(acc[mi][ni][0], acc[mi][ni][1]);
            sT[(r + 8) * RT_STRIDE + c2] = packh2(acc[mi][ni][2], acc[mi][ni][3]);
        }
    __syncthreads();

    // Re-partition: 128 rows x 2 heads x 32 h2-pairs = 8192 units, 32/thread.
    // cos/sin duplicate halves (cos[d] == cos[d+64]), so one float2 each.
#pragma unroll
    for (int i = 0; i < 32; i++) {
        int idx  = tid + i * 256;
        int d2   = idx & 31;           // h2 index within [0,64) dims
        int head = (idx >> 5) & 1;
        int row  = idx >> 6;
        int grow = (int)rbase + row;
        int pos  = grow & (Sc - 1);
        float2 cs = *(const float2*)(cb + pos * HDc + 2 * d2);
        float2 sn = *(const float2*)(sb + pos * HDc + 2 * d2);
        uint32_t u0 = sT[row * RT_STRIDE + head * 64 + d2];
        uint32_t u1 = sT[row * RT_STRIDE + head * 64 + d2 + 32];
        __half2 h0 = *(__half2*)&u0, h1 = *(__half2*)&u1;
        float x1a = __half2float(h0.x), x1b = __half2float(h0.y);
        float x2a = __half2float(h1.x), x2b = __half2float(h1.y);
        uint32_t o0 = packh2(x1a * cs.x - x2a * sn.x, x1b * cs.y - x2b * sn.y);
        uint32_t o1 = packh2(x2a * cs.x + x1a * sn.x, x2b * cs.y + x1b * sn.y);
        int gcol = cbase + head * 128 + 2 * d2;
        *(uint32_t*)(Ch + (size_t)grow * ldc + gcol)      = o0;
        *(uint32_t*)(Ch + (size_t)grow * ldc + gcol + 64) = o1;
    }
}

// Merged QKV projection with fused rope on Q,K: grid = (HS/256, MR/128, 3)
__global__ __launch_bounds__(256) void gemm_qkv(
    const __half* __restrict__ A,
    const __half* __restrict__ b0, const __half* __restrict__ b1,
    const __half* __restrict__ b2,
    __half* __restrict__ c0, __half* __restrict__ c1, __half* __restrict__ c2,
    const float* __restrict__ cb, const float* __restrict__ sb)
{
    extern __shared__ char dsm[];
    const __half* B = (blockIdx.z == 0) ? b0 : (blockIdx.z == 1) ? b1 : b2;
    __half*       C = (blockIdx.z == 0) ? c0 : (blockIdx.z == 1) ? c1 : c2;
    gemm_body<false>(A, B, C, HS, HS, HS, HS, dsm, cb, sb, blockIdx.z < 2);
}

// O projection (fp32 out): grid = (HS/256, MR/128)
__global__ __launch_bounds__(256) void gemm_o(
    const __half* __restrict__ A, const __half* __restrict__ B,
    float* __restrict__ C)
{
    extern __shared__ char dsm[];
    gemm_body<true>(A, B, C, HS, HS, HS, HS, dsm, nullptr, nullptr, false);
}

// ---------------------------------------------------------------------------
// FA2-style fused causal flash attention (unchanged from round 7/8).
// ---------------------------------------------------------------------------
constexpr int F_Q    = 0;
constexpr int F_K0   = 32768;
constexpr int F_V0   = 98304;
constexpr int F_SMEM = 163840;

__global__ __launch_bounds__(256) void flash_h(
    const __half* __restrict__ Q, const __half* __restrict__ K,
    const __half* __restrict__ V, __half* __restrict__ O)
{
    extern __shared__ char dsm[];
    const uint32_t sbase = smem_u32(dsm);
    const uint32_t aQ = sbase + F_Q;

    const int qt = (int)gridDim.x - 1 - (int)blockIdx.x;
    const int bh = blockIdx.y;
    const int b = bh >> 4, h = bh & 15;
    const int tid  = threadIdx.x;
    const int lane = tid & 31, warp = tid >> 5;
    const int g = lane >> 2, tg = lane & 3;
    const int wr = warp * 16;

    const __half* Qb = Q + (size_t)(b * Sc + qt * 128) * HS + h * HDc;
    const __half* Kb = K + (size_t)(b * Sc) * HS + h * HDc;
    const __half* Vb = V + (size_t)(b * Sc) * HS + h * HDc;

    auto load_tile = [&](uint32_t adst, const __half* src, int ktile) {
        const __half* p = src + (size_t)(ktile * 128) * HS;
#pragma unroll
        for (int i = 0; i < 8; i++) {
            int idx = tid + i * 256;
            int r = idx >> 4, u = idx & 15;
            cpa16(adst + r * 256 + ((u ^ (r & 7)) << 4), p + (size_t)r * HS + u * 8);
        }
    };

#pragma unroll
    for (int i = 0; i < 8; i++) {
        int idx = tid + i * 256;
        int r = idx >> 4, u = idx & 15;
        cpa16(aQ + r * 256 + ((u ^ (r & 7)) << 4), Qb + (size_t)r * HS + u * 8);
    }
    load_tile(sbase + F_K0, Kb, 0);
    load_tile(sbase + F_V0, Vb, 0);
    cpa_commit();

    float acc_o[16][4];
#pragma unroll
    for (int ni = 0; ni < 16; ni++)
#pragma unroll
        for (int j = 0; j < 4; j++) acc_o[ni][j] = 0.f;
    float m0 = -1e30f, m1 = -1e30f, l0 = 0.f, l1 = 0.f;

    for (int kt = 0; kt <= qt; kt++) {
        cpa_wait<0>();
        __syncthreads();

        if (kt < qt) {
            const int nb = (kt + 1) & 1;
            load_tile(sbase + F_K0 + nb * 32768, Kb, kt + 1);
            cpa_commit();
            load_tile(sbase + F_V0 + nb * 32768, Vb, kt + 1);
            cpa_commit();
        }
        const uint32_t cK = sbase + F_K0 + (kt & 1) * 32768;
        const uint32_t cV = sbase + F_V0 + (kt & 1) * 32768;

        float accs[16][4];
#pragma unroll
        for (int ni = 0; ni < 16; ni++)
#pragma unroll
            for (int j = 0; j < 4; j++) accs[ni][j] = 0.f;

#pragma unroll
        for (int ks = 0; ks < 8; ks++) {
            uint32_t a[4];
            {
                int row = wr + (lane & 15);
                int u   = 2 * ks + (lane >> 4);
                ldsm4(a, aQ + row * 256 + ((u ^ (row & 7)) << 4));
            }
#pragma unroll
            for (int nj = 0; nj < 8; nj++) {
                int row = 16 * nj + (lane & 7) + ((lane & 16) >> 1);
                int u   = 2 * ks + ((lane >> 3) & 1);
                uint32_t t[4];
                ldsm4(t, cK + row * 256 + ((u ^ (row & 7)) << 4));
                mma16(accs[2 * nj],     a, t);
                mma16(accs[2 * nj + 1], a, t + 2);
            }
        }

        const bool diag = (kt == qt);
        const int r0 = wr + g, r1 = r0 + 8;
#pragma unroll
        for (int ni = 0; ni < 16; ni++) {
            int c0 = ni * 8 + tg * 2, c1 = c0 + 1;
            accs[ni][0] *= SCALE; accs[ni][1] *= SCALE;
            accs[ni][2] *= SCALE; accs[ni][3] *= SCALE;
            if (diag) {
                if (c0 > r0) accs[ni][0] = -1e30f;
                if (c1 > r0) accs[ni][1] = -1e30f;
                if (c0 > r1) accs[ni][2] = -1e30f;
                if (c1 > r1) accs[ni][3] = -1e30f;
            }
        }

        float lm0 = -1e30f, lm1 = -1e30f;
#pragma unroll
        for (int ni = 0; ni < 16; ni++) {
            lm0 = fmaxf(lm0, fmaxf(accs[ni][0], accs[ni][1]));
            lm1 = fmaxf(lm1, fmaxf(accs[ni][2], accs[ni][3]));
        }
        lm0 = fmaxf(lm0, __shfl_xor_sync(0xffffffffu, lm0, 1));
        lm0 = fmaxf(lm0, __shfl_xor_sync(0xffffffffu, lm0, 2));
        lm1 = fmaxf(lm1, __shfl_xor_sync(0xffffffffu, lm1, 1));
        lm1 = fmaxf(lm1, __shfl_xor_sync(0xffffffffu, lm1, 2));

        float mn0 = fmaxf(m0, lm0), mn1 = fmaxf(m1, lm1);
        float cr0 = __expf(m0 - mn0), cr1 = __expf(m1 - mn1);
        m0 = mn0; m1 = mn1;

        uint32_t ph[16][2];
        float ls0 = 0.f, ls1 = 0.f;
#pragma unroll
        for (int ni = 0; ni < 16; ni++) {
            float p0 = __expf(accs[ni][0] - mn0);
            float p1 = __expf(accs[ni][1] - mn0);
            float p2 = __expf(accs[ni][2] - mn1);
            float p3 = __expf(accs[ni][3] - mn1);
            ls0 += p0 + p1; ls1 += p2 + p3;
            ph[ni][0] = packh2(p0, p1);
            ph[ni][1] = packh2(p2, p3);
            acc_o[ni][0] *= cr0; acc_o[ni][1] *= cr0;
            acc_o[ni][2] *= cr1; acc_o[ni][3] *= cr1;
        }
        ls0 += __shfl_xor_sync(0xffffffffu, ls0, 1);
        ls0 += __shfl_xor_sync(0xffffffffu, ls0, 2);
        ls1 += __shfl_xor_sync(0xffffffffu, ls1, 1);
        ls1 += __shfl_xor_sync(0xffffffffu, ls1, 2);
        l0 = l0 * cr0 + ls0;
        l1 = l1 * cr1 + ls1;

#pragma unroll
        for (int ks = 0; ks < 8; ks++) {
            uint32_t a[4] = { ph[2 * ks][0], ph[2 * ks][1],
                              ph[2 * ks + 1][0], ph[2 * ks + 1][1] };
#pragma unroll
            for (int nj = 0; nj < 8; nj++) {
                int rowv = 16 * ks + (lane & 7) + (lane & 8);
                int u    = 2 * nj + (lane >> 4);
                uint32_t t[4];
                ldsm4t(t, cV + rowv * 256 + ((u ^ (rowv & 7)) << 4));
                mma16(acc_o[2 * nj],     a, t);
                mma16(acc_o[2 * nj + 1], a, t + 2);
            }
        }
    }

    __half* Ob = O + (size_t)(b * Sc + qt * 128) * HS + h * HDc;
    const float inv0 = 1.f / l0, inv1 = 1.f / l1;
    const int r0 = wr + g, r1 = r0 + 8;
#pragma unroll
    for (int ni = 0; ni < 16; ni++) {
        int c = ni * 8 + tg * 2;
        *(uint32_t*)(Ob + (size_t)r0 * HS + c) =
            packh2(acc_o[ni][0] * inv0, acc_o[ni][1] * inv0);
        *(uint32_t*)(Ob + (size_t)r1 * HS + c) =
            packh2(acc_o[ni][2] * inv1, acc_o[ni][3] * inv1);
    }
}

// ---------------------------------------------------------------------------
// Launcher
// ---------------------------------------------------------------------------
extern "C" void kernel_launch(void* const* d_in, const int* in_sizes, int n_in,
                              void* d_out, int out_size)
{
    const float* hs = (const float*)d_in[0];
    const float* wq = (const float*)d_in[1];
    const float* wk = (const float*)d_in[2];
    const float* wv = (const float*)d_in[3];
    const float* wo = (const float*)d_in[4];
    const float* cb = (const float*)d_in[5];
    const float* sb = (const float*)d_in[6];
    float* out = (float*)d_out;

    __half *qp, *kp, *vp, *aop, *hsp, *wqp, *wkp, *wvp, *wop;
    cudaGetSymbolAddress((void**)&qp,  g_q);
    cudaGetSymbolAddress((void**)&kp,  g_k);
    cudaGetSymbolAddress((void**)&vp,  g_v);
    cudaGetSymbolAddress((void**)&aop, g_ao);
    cudaGetSymbolAddress((void**)&hsp, g_hs);
    cudaGetSymbolAddress((void**)&wqp, g_wq);
    cudaGetSymbolAddress((void**)&wkp, g_wk);
    cudaGetSymbolAddress((void**)&wvp, g_wv);
    cudaGetSymbolAddress((void**)&wop, g_wo);

    cudaFuncSetAttribute(gemm_qkv, cudaFuncAttributeMaxDynamicSharedMemorySize, GH_SMEM);
    cudaFuncSetAttribute(gemm_o,   cudaFuncAttributeMaxDynamicSharedMemorySize, GH_SMEM);
    cudaFuncSetAttribute(flash_h,  cudaFuncAttributeMaxDynamicSharedMemorySize, F_SMEM);

    dim3 blk(256);

    round_all<<<dim3(MR * HS / 4 / 256, 5), blk>>>(
        (const float4*)hs, (const float4*)wq, (const float4*)wk,
        (const float4*)wv, (const float4*)wo,
        (uint2*)hsp, (uint2*)wqp, (uint2*)wkp, (uint2*)wvp, (uint2*)wop);

    gemm_qkv<<<dim3(HS / GB_N, MR / 128, 3), blk, GH_SMEM>>>(
        hsp, wqp, wkp, wvp, qp, kp, vp, cb, sb);

    flash_h<<<dim3(Sc / 128, BHc), blk, F_SMEM>>>(qp, kp, vp, aop);

    gemm_o<<<dim3(HS / GB_N, MR / 128), blk, GH_SMEM>>>(aop, wop, out);
}

// round 10
// speedup vs baseline: 3.5709x; 1.0851x over previous
#include <cuda_runtime.h>
#include <cuda_fp16.h>
#include <cstdint>
#include <cstddef>

// Problem constants
constexpr int Bc  = 2;
constexpr int Sc  = 2048;
constexpr int HS  = 2048;
constexpr int NHc = 16;
constexpr int HDc = 128;
constexpr int MR  = Bc * Sc;    // 4096 rows of (b, s)
constexpr int BHc = Bc * NHc;   // 32 (batch*heads)
constexpr float SCALE = 0.08838834764831845f;  // 1/sqrt(128)

// Scratch (device globals — allocation-free per harness rules)
__device__ __half g_q [MR * HS];
__device__ __half g_k [MR * HS];
__device__ __half g_v [MR * HS];
__device__ __half g_ao[MR * HS];
__device__ __half g_hs[MR * HS];
__device__ __half g_wq[HS * HS];
__device__ __half g_wk[HS * HS];
__device__ __half g_wv[HS * HS];
__device__ __half g_wo[HS * HS];

// ---------------------------------------------------------------------------
// Helpers
// ---------------------------------------------------------------------------
__device__ __forceinline__ uint32_t smem_u32(const void* p) {
    uint32_t a;
    asm("{ .reg .u64 t; cvta.to.shared.u64 t, %1; cvt.u32.u64 %0, t; }"
        : "=r"(a) : "l"(p));
    return a;
}
__device__ __forceinline__ void cpa16(uint32_t dst, const void* src) {
    asm volatile("cp.async.cg.shared.global [%0], [%1], 16;"
                 :: "r"(dst), "l"(src) : "memory");
}
__device__ __forceinline__ void cpa_commit() {
    asm volatile("cp.async.commit_group;" ::: "memory");
}
template <int N>
__device__ __forceinline__ void cpa_wait() {
    asm volatile("cp.async.wait_group %0;" :: "n"(N) : "memory");
}
__device__ __forceinline__ void ldsm4(uint32_t* r, uint32_t a) {
    asm volatile("ldmatrix.sync.aligned.m8n8.x4.shared.b16 {%0,%1,%2,%3}, [%4];"
                 : "=r"(r[0]), "=r"(r[1]), "=r"(r[2]), "=r"(r[3]) : "r"(a));
}
__device__ __forceinline__ void ldsm4t(uint32_t* r, uint32_t a) {
    asm volatile("ldmatrix.sync.aligned.m8n8.x4.trans.shared.b16 {%0,%1,%2,%3}, [%4];"
                 : "=r"(r[0]), "=r"(r[1]), "=r"(r[2]), "=r"(r[3]) : "r"(a));
}
__device__ __forceinline__ void mma16(float* c, const uint32_t* a, const uint32_t* b) {
    asm volatile(
        "mma.sync.aligned.m16n8k16.row.col.f32.f16.f16.f32 "
        "{%0,%1,%2,%3},{%4,%5,%6,%7},{%8,%9},{%0,%1,%2,%3};\n"
        : "+f"(c[0]), "+f"(c[1]), "+f"(c[2]), "+f"(c[3])
        : "r"(a[0]), "r"(a[1]), "r"(a[2]), "r"(a[3]),
          "r"(b[0]), "r"(b[1]));
}
__device__ __forceinline__ uint32_t packh2(float a, float b) {
    __half2 h = __floats2half2_rn(a, b);
    return *(uint32_t*)&h;
}

// ---------------------------------------------------------------------------
// Merged fp16 conversion: grid = (8192, 5). y=0: hs; y=1..4: weights.
// ---------------------------------------------------------------------------
__global__ __launch_bounds__(256) void round_all(
    const float4* __restrict__ hs, const float4* __restrict__ w0,
    const float4* __restrict__ w1, const float4* __restrict__ w2,
    const float4* __restrict__ w3,
    uint2* __restrict__ ohs, uint2* __restrict__ o0, uint2* __restrict__ o1,
    uint2* __restrict__ o2, uint2* __restrict__ o3)
{
    const int y = blockIdx.y;
    const float4* in  = (y == 0) ? hs : (y == 1) ? w0 : (y == 2) ? w1
                      : (y == 3) ? w2 : w3;
    uint2*        out = (y == 0) ? ohs : (y == 1) ? o0 : (y == 2) ? o1
                      : (y == 3) ? o2 : o3;
    const int n4 = (y == 0) ? (MR * HS / 4) : (HS * HS / 4);
    int i = blockIdx.x * 256 + threadIdx.x;
    if (i < n4) {
        float4 v = in[i];
        uint2 o;
        o.x = packh2(v.x, v.y);
        o.y = packh2(v.z, v.w);
        out[i] = o;
    }
}

// ---------------------------------------------------------------------------
// fp16 TN GEMM: C[M,N] = A[M,K] * B[N,K]^T
// Block tile 128x128, 4 warps (2x2) of 64x64, BK=64 halves, 128 threads.
// 3-stage cp.async ring (32KB/stage = 96KB) -> 2 CTAs/SM.
// Optional fused RoPE epilogue (doRope).
// ---------------------------------------------------------------------------
constexpr int GB_N      = 128;
constexpr int GH_A      = 128 * 128;          // bytes per operand per stage
constexpr int GH_STAGE  = 2 * GH_A;           // 32768
constexpr int GH_SMEM   = 3 * GH_STAGE;       // 98304
constexpr int RT_STRIDE = 68;                 // h2 per staged row (64 + pad)

template <bool OUTF>
__device__ __forceinline__ void gemm_body(
    const __half* __restrict__ A, const __half* __restrict__ B,
    void* __restrict__ Cv, int lda, int ldb, int ldc, int K, char* dsm,
    const float* __restrict__ cb, const float* __restrict__ sb, bool doRope)
{
    const uint32_t sbase = smem_u32(dsm);
    const int tid  = threadIdx.x;               // 0..127
    const int lane = tid & 31, warp = tid >> 5; // warp 0..3
    const int g = lane >> 2, tg = lane & 3;
    const int wm = (warp >> 1) * 64;            // 0 or 64
    const int wn = (warp & 1) * 64;             // 0 or 64

    const __half* Ab = A + (size_t)blockIdx.y * 128 * lda;
    const __half* Bb = B + (size_t)blockIdx.x * GB_N * ldb;

    float acc[4][8][4];
#pragma unroll
    for (int mi = 0; mi < 4; mi++)
#pragma unroll
        for (int ni = 0; ni < 8; ni++)
#pragma unroll
            for (int j = 0; j < 4; j++) acc[mi][ni][j] = 0.f;

    auto issue = [&](int s, int k0) {
        const uint32_t stA = sbase + s * GH_STAGE;
        const uint32_t stB = stA + GH_A;
#pragma unroll
        for (int i = 0; i < 8; i++) {            // A: 1024 16B units
            int idx = tid + i * 128;
            int r = idx >> 3, u = idx & 7;
            cpa16(stA + r * 128 + ((u ^ (r & 7)) << 4),
                  Ab + (size_t)r * lda + k0 + u * 8);
        }
#pragma unroll
        for (int i = 0; i < 8; i++) {            // B: 1024 16B units
            int idx = tid + i * 128;
            int r = idx >> 3, u = idx & 7;
            cpa16(stB + r * 128 + ((u ^ (r & 7)) << 4),
                  Bb + (size_t)r * ldb + k0 + u * 8);
        }
        cpa_commit();
    };

    const int nchunk = K / 64;                   // 32
    issue(0, 0); issue(1, 64);

    for (int c = 0; c < nchunk; c++) {
        cpa_wait<1>();
        __syncthreads();   // stage c ready; all warps done with stage c-1

        // Buffer (c+2)%3 was last READ at iter c-1; barrier orders those reads.
        if (c + 2 < nchunk) issue((c + 2) % 3, (c + 2) * 64);
        else                cpa_commit();        // uniform group count

        const int s = c % 3;
        const uint32_t stA = sbase + s * GH_STAGE;
        const uint32_t stB = stA + GH_A;

#pragma unroll
        for (int ks = 0; ks < 4; ks++) {
            uint32_t af[4][4];
#pragma unroll
            for (int mi = 0; mi < 4; mi++) {
                int row = wm + 16 * mi + (lane & 15);
                int u   = 2 * ks + (lane >> 4);
                ldsm4(af[mi], stA + row * 128 + ((u ^ (row & 7)) << 4));
            }
#pragma unroll
            for (int nj = 0; nj < 4; nj++) {
                int row = wn + 16 * nj + (lane & 7) + ((lane & 16) >> 1);
                int u   = 2 * ks + ((lane >> 3) & 1);
                uint32_t t[4];
                ldsm4(t, stB + row * 128 + ((u ^ (row & 7)) << 4));
#pragma unroll
                for (int mi = 0; mi < 4; mi++) {
                    mma16(acc[mi][2 * nj],     af[mi], t);
                    mma16(acc[mi][2 * nj + 1], af[mi], t + 2);
                }
            }
        }
    }

    const size_t rbase = (size_t)blockIdx.y * 128;
    const int cbase = blockIdx.x * GB_N;

    if (OUTF) {
        float* Cf = (float*)Cv;
#pragma unroll
        for (int mi = 0; mi < 4; mi++)
#pragma unroll
            for (int ni = 0; ni < 8; ni++) {
                size_t r = rbase + wm + mi * 16 + g;
                int    cc = cbase + wn + ni * 8 + tg * 2;
                float2 v0; v0.x = acc[mi][ni][0]; v0.y = acc[mi][ni][1];
                float2 v1; v1.x = acc[mi][ni][2]; v1.y = acc[mi][ni][3];
                *(float2*)(Cf + r * ldc + cc)       = v0;
                *(float2*)(Cf + (r + 8) * ldc + cc) = v1;
            }
        return;
    }

    __half* Ch = (__half*)Cv;
    if (!doRope) {
#pragma unroll
        for (int mi = 0; mi < 4; mi++)
#pragma unroll
            for (int ni = 0; ni < 8; ni++) {
                size_t r = rbase + wm + mi * 16 + g;
                int    cc = cbase + wn + ni * 8 + tg * 2;
                *(uint32_t*)(Ch + r * ldc + cc)       = packh2(acc[mi][ni][0], acc[mi][ni][1]);
                *(uint32_t*)(Ch + (r + 8) * ldc + cc) = packh2(acc[mi][ni][2], acc[mi][ni][3]);
            }
        return;
    }

    // ---- fused RoPE epilogue (this 128-wide N tile == exactly one head) ----
    __syncthreads();                 // protect ring reads before overwrite
    uint32_t* sT = (uint32_t*)dsm;   // 128 rows x 68 h2
#pragma unroll
    for (int mi = 0; mi < 4; mi++)
#pragma unroll
        for (int ni = 0; ni < 8; ni++) {
            int r  = wm + mi * 16 + g;
            int c2 = (wn + ni * 8 + tg * 2) >> 1;
            sT[r * RT_STRIDE + c2]       = packh2(acc[mi][ni][0], acc[mi][ni][1]);
            sT[(r + 8) * RT_STRIDE + c2] = packh2(acc[mi][ni][2], acc[mi][ni][3]);
        }
    __syncthreads();

    // 128 rows x 32 h2-dims = 4096 units, 32 per thread.
    // cos[d] == cos[d+64] (concat construction) -> one float2 per pair.
#pragma unroll
    for (int i = 0; i < 32; i++) {
        int idx  = tid + i * 128;
        int d2   = idx & 31;
        int row  = idx >> 5;
        int grow = (int)rbase + row;
        int pos  = grow & (Sc - 1);
        float2 cs = *(const float2*)(cb + pos * HDc + 2 * d2);
        float2 sn = *(const float2*)(sb + pos * HDc + 2 * d2);
        uint32_t u0 = sT[row * RT_STRIDE + d2];
        uint32_t u1 = sT[row * RT_STRIDE + d2 + 32];
        __half2 h0 = *(__half2*)&u0, h1 = *(__half2*)&u1;
        float x1a = __half2float(h0.x), x1b = __half2float(h0.y);
        float x2a = __half2float(h1.x), x2b = __half2float(h1.y);
        uint32_t o0 = packh2(x1a * cs.x - x2a * sn.x, x1b * cs.y - x2b * sn.y);
        uint32_t o1 = packh2(x2a * cs.x + x1a * sn.x, x2b * cs.y + x1b * sn.y);
        int gcol = cbase + 2 * d2;
        *(uint32_t*)(Ch + (size_t)grow * ldc + gcol)      = o0;
        *(uint32_t*)(Ch + (size_t)grow * ldc + gcol + 64) = o1;
    }
}

// Merged QKV projection with fused rope on Q,K: grid = (HS/128, MR/128, 3)
__global__ __launch_bounds__(128) void gemm_qkv(
    const __half* __restrict__ A,
    const __half* __restrict__ b0, const __half* __restrict__ b1,
    const __half* __restrict__ b2,
    __half* __restrict__ c0, __half* __restrict__ c1, __half* __restrict__ c2,
    const float* __restrict__ cb, const float* __restrict__ sb)
{
    extern __shared__ char dsm[];
    const __half* B = (blockIdx.z == 0) ? b0 : (blockIdx.z == 1) ? b1 : b2;
    __half*       C = (blockIdx.z == 0) ? c0 : (blockIdx.z == 1) ? c1 : c2;
    gemm_body<false>(A, B, C, HS, HS, HS, HS, dsm, cb, sb, blockIdx.z < 2);
}

// O projection (fp32 out): grid = (HS/128, MR/128)
__global__ __launch_bounds__(128) void gemm_o(
    const __half* __restrict__ A, const __half* __restrict__ B,
    float* __restrict__ C)
{
    extern __shared__ char dsm[];
    gemm_body<true>(A, B, C, HS, HS, HS, HS, dsm, nullptr, nullptr, false);
}

// ---------------------------------------------------------------------------
// FA2-style fused causal flash attention (unchanged from rounds 7-9).
// ---------------------------------------------------------------------------
constexpr int F_Q    = 0;
constexpr int F_K0   = 32768;
constexpr int F_V0   = 98304;
constexpr int F_SMEM = 163840;

__global__ __launch_bounds__(256) void flash_h(
    const __half* __restrict__ Q, const __half* __restrict__ K,
    const __half* __restrict__ V, __half* __restrict__ O)
{
    extern __shared__ char dsm[];
    const uint32_t sbase = smem_u32(dsm);
    const uint32_t aQ = sbase + F_Q;

    const int qt = (int)gridDim.x - 1 - (int)blockIdx.x;
    const int bh = blockIdx.y;
    const int b = bh >> 4, h = bh & 15;
    const int tid  = threadIdx.x;
    const int lane = tid & 31, warp = tid >> 5;
    const int g = lane >> 2, tg = lane & 3;
    const int wr = warp * 16;

    const __half* Qb = Q + (size_t)(b * Sc + qt * 128) * HS + h * HDc;
    const __half* Kb = K + (size_t)(b * Sc) * HS + h * HDc;
    const __half* Vb = V + (size_t)(b * Sc) * HS + h * HDc;

    auto load_tile = [&](uint32_t adst, const __half* src, int ktile) {
        const __half* p = src + (size_t)(ktile * 128) * HS;
#pragma unroll
        for (int i = 0; i < 8; i++) {
            int idx = tid + i * 256;
            int r = idx >> 4, u = idx & 15;
            cpa16(adst + r * 256 + ((u ^ (r & 7)) << 4), p + (size_t)r * HS + u * 8);
        }
    };

#pragma unroll
    for (int i = 0; i < 8; i++) {
        int idx = tid + i * 256;
        int r = idx >> 4, u = idx & 15;
        cpa16(aQ + r * 256 + ((u ^ (r & 7)) << 4), Qb + (size_t)r * HS + u * 8);
    }
    load_tile(sbase + F_K0, Kb, 0);
    load_tile(sbase + F_V0, Vb, 0);
    cpa_commit();

    float acc_o[16][4];
#pragma unroll
    for (int ni = 0; ni < 16; ni++)
#pragma unroll
        for (int j = 0; j < 4; j++) acc_o[ni][j] = 0.f;
    float m0 = -1e30f, m1 = -1e30f, l0 = 0.f, l1 = 0.f;

    for (int kt = 0; kt <= qt; kt++) {
        cpa_wait<0>();
        __syncthreads();

        if (kt < qt) {
            const int nb = (kt + 1) & 1;
            load_tile(sbase + F_K0 + nb * 32768, Kb, kt + 1);
            cpa_commit();
            load_tile(sbase + F_V0 + nb * 32768, Vb, kt + 1);
            cpa_commit();
        }
        const uint32_t cK = sbase + F_K0 + (kt & 1) * 32768;
        const uint32_t cV = sbase + F_V0 + (kt & 1) * 32768;

        float accs[16][4];
#pragma unroll
        for (int ni = 0; ni < 16; ni++)
#pragma unroll
            for (int j = 0; j < 4; j++) accs[ni][j] = 0.f;

#pragma unroll
        for (int ks = 0; ks < 8; ks++) {
            uint32_t a[4];
            {
                int row = wr + (lane & 15);
                int u   = 2 * ks + (lane >> 4);
                ldsm4(a, aQ + row * 256 + ((u ^ (row & 7)) << 4));
            }
#pragma unroll
            for (int nj = 0; nj < 8; nj++) {
                int row = 16 * nj + (lane & 7) + ((lane & 16) >> 1);
                int u   = 2 * ks + ((lane >> 3) & 1);
                uint32_t t[4];
                ldsm4(t, cK + row * 256 + ((u ^ (row & 7)) << 4));
                mma16(accs[2 * nj],     a, t);
                mma16(accs[2 * nj + 1], a, t + 2);
            }
        }

        const bool diag = (kt == qt);
        const int r0 = wr + g, r1 = r0 + 8;
#pragma unroll
        for (int ni = 0; ni < 16; ni++) {
            int c0 = ni * 8 + tg * 2, c1 = c0 + 1;
            accs[ni][0] *= SCALE; accs[ni][1] *= SCALE;
            accs[ni][2] *= SCALE; accs[ni][3] *= SCALE;
            if (diag) {
                if (c0 > r0) accs[ni][0] = -1e30f;
                if (c1 > r0) accs[ni][1] = -1e30f;
                if (c0 > r1) accs[ni][2] = -1e30f;
                if (c1 > r1) accs[ni][3] = -1e30f;
            }
        }

        float lm0 = -1e30f, lm1 = -1e30f;
#pragma unroll
        for (int ni = 0; ni < 16; ni++) {
            lm0 = fmaxf(lm0, fmaxf(accs[ni][0], accs[ni][1]));
            lm1 = fmaxf(lm1, fmaxf(accs[ni][2], accs[ni][3]));
        }
        lm0 = fmaxf(lm0, __shfl_xor_sync(0xffffffffu, lm0, 1));
        lm0 = fmaxf(lm0, __shfl_xor_sync(0xffffffffu, lm0, 2));
        lm1 = fmaxf(lm1, __shfl_xor_sync(0xffffffffu, lm1, 1));
        lm1 = fmaxf(lm1, __shfl_xor_sync(0xffffffffu, lm1, 2));

        float mn0 = fmaxf(m0, lm0), mn1 = fmaxf(m1, lm1);
        float cr0 = __expf(m0 - mn0), cr1 = __expf(m1 - mn1);
        m0 = mn0; m1 = mn1;

        uint32_t ph[16][2];
        float ls0 = 0.f, ls1 = 0.f;
#pragma unroll
        for (int ni = 0; ni < 16; ni++) {
            float p0 = __expf(accs[ni][0] - mn0);
            float p1 = __expf(accs[ni][1] - mn0);
            float p2 = __expf(accs[ni][2] - mn1);
            float p3 = __expf(accs[ni][3] - mn1);
            ls0 += p0 + p1; ls1 += p2 + p3;
            ph[ni][0] = packh2(p0, p1);
            ph[ni][1] = packh2(p2, p3);
            acc_o[ni][0] *= cr0; acc_o[ni][1] *= cr0;
            acc_o[ni][2] *= cr1; acc_o[ni][3] *= cr1;
        }
        ls0 += __shfl_xor_sync(0xffffffffu, ls0, 1);
        ls0 += __shfl_xor_sync(0xffffffffu, ls0, 2);
        ls1 += __shfl_xor_sync(0xffffffffu, ls1, 1);
        ls1 += __shfl_xor_sync(0xffffffffu, ls1, 2);
        l0 = l0 * cr0 + ls0;
        l1 = l1 * cr1 + ls1;

#pragma unroll
        for (int ks = 0; ks < 8; ks++) {
            uint32_t a[4] = { ph[2 * ks][0], ph[2 * ks][1],
                              ph[2 * ks + 1][0], ph[2 * ks + 1][1] };
#pragma unroll
            for (int nj = 0; nj < 8; nj++) {
                int rowv = 16 * ks + (lane & 7) + (lane & 8);
                int u    = 2 * nj + (lane >> 4);
                uint32_t t[4];
                ldsm4t(t, cV + rowv * 256 + ((u ^ (rowv & 7)) << 4));
                mma16(acc_o[2 * nj],     a, t);
                mma16(acc_o[2 * nj + 1], a, t + 2);
            }
        }
    }

    __half* Ob = O + (size_t)(b * Sc + qt * 128) * HS + h * HDc;
    const float inv0 = 1.f / l0, inv1 = 1.f / l1;
    const int r0 = wr + g, r1 = r0 + 8;
#pragma unroll
    for (int ni = 0; ni < 16; ni++) {
        int c = ni * 8 + tg * 2;
        *(uint32_t*)(Ob + (size_t)r0 * HS + c) =
            packh2(acc_o[ni][0] * inv0, acc_o[ni][1] * inv0);
        *(uint32_t*)(Ob + (size_t)r1 * HS + c) =
            packh2(acc_o[ni][2] * inv1, acc_o[ni][3] * inv1);
    }
}

// ---------------------------------------------------------------------------
// Launcher
// ---------------------------------------------------------------------------
extern "C" void kernel_launch(void* const* d_in, const int* in_sizes, int n_in,
                              void* d_out, int out_size)
{
    const float* hs = (const float*)d_in[0];
    const float* wq = (const float*)d_in[1];
    const float* wk = (const float*)d_in[2];
    const float* wv = (const float*)d_in[3];
    const float* wo = (const float*)d_in[4];
    const float* cb = (const float*)d_in[5];
    const float* sb = (const float*)d_in[6];
    float* out = (float*)d_out;

    __half *qp, *kp, *vp, *aop, *hsp, *wqp, *wkp, *wvp, *wop;
    cudaGetSymbolAddress((void**)&qp,  g_q);
    cudaGetSymbolAddress((void**)&kp,  g_k);
    cudaGetSymbolAddress((void**)&vp,  g_v);
    cudaGetSymbolAddress((void**)&aop, g_ao);
    cudaGetSymbolAddress((void**)&hsp, g_hs);
    cudaGetSymbolAddress((void**)&wqp, g_wq);
    cudaGetSymbolAddress((void**)&wkp, g_wk);
    cudaGetSymbolAddress((void**)&wvp, g_wv);
    cudaGetSymbolAddress((void**)&wop, g_wo);

    cudaFuncSetAttribute(gemm_qkv, cudaFuncAttributeMaxDynamicSharedMemorySize, GH_SMEM);
    cudaFuncSetAttribute(gemm_o,   cudaFuncAttributeMaxDynamicSharedMemorySize, GH_SMEM);
    cudaFuncSetAttribute(flash_h,  cudaFuncAttributeMaxDynamicSharedMemorySize, F_SMEM);

    round_all<<<dim3(MR * HS / 4 / 256, 5), 256>>>(
        (const float4*)hs, (const float4*)wq, (const float4*)wk,
        (const float4*)wv, (const float4*)wo,
        (uint2*)hsp, (uint2*)wqp, (uint2*)wkp, (uint2*)wvp, (uint2*)wop);

    gemm_qkv<<<dim3(HS / GB_N, MR / 128, 3), 128, GH_SMEM>>>(
        hsp, wqp, wkp, wvp, qp, kp, vp, cb, sb);

    flash_h<<<dim3(Sc / 128, BHc), 256, F_SMEM>>>(qp, kp, vp, aop);

    gemm_o<<<dim3(HS / GB_N, MR / 128), 128, GH_SMEM>>>(aop, wop, out);
}